// round 8
// baseline (speedup 1.0000x reference)
#include <cuda_runtime.h>
#include <cstdint>

// ---------------- problem constants ----------------
#define H_HEADS 16
#define DMODEL  1024
#define BATCH   4
#define SEQ     2048
#define MTOT    (BATCH * SEQ)          // 8192

// ---------------- scratch (static device globals; no allocs) ----------------
__device__ float g_q[(size_t)BATCH * H_HEADS * SEQ * 64];   // tf32, pre-scaled 0.125*log2e
__device__ float g_k[(size_t)BATCH * H_HEADS * SEQ * 64];   // tf32
__device__ float g_v[(size_t)BATCH * H_HEADS * SEQ * 64];   // tf32
__device__ float g_ctx[(size_t)BATCH * SEQ * DMODEL];       // tf32-rounded (B,S,H*dk)
__device__ float g_ain[3][(size_t)MTOT * DMODEL];           // tf32 copies of q/k/v inputs
__device__ float g_win[4][(size_t)DMODEL * DMODEL];         // tf32 copies of Wq/Wk/Wv/Wo

// ---------------- helpers ----------------
__device__ __forceinline__ uint32_t smem_u32(const void* p) {
    uint32_t a;
    asm("{ .reg .u64 t; cvta.to.shared.u64 t, %1; cvt.u32.u64 %0, t; }"
        : "=r"(a) : "l"(p));
    return a;
}

__device__ __forceinline__ uint32_t f2tf(float x) {
    uint32_t r;
    asm("cvt.rna.tf32.f32 %0, %1;" : "=r"(r) : "f"(x));
    return r;
}

__device__ __forceinline__ float ex2(float x) {
    float y;
    asm("ex2.approx.f32 %0, %1;" : "=f"(y) : "f"(x));
    return y;
}

// D += A(m16k8, tf32) * B(k8n8, tf32)   (row.col)
__device__ __forceinline__ void mma_tf32(float* c, const uint32_t* a, const uint32_t* b) {
    asm volatile(
        "mma.sync.aligned.m16n8k8.row.col.f32.tf32.tf32.f32 "
        "{%0,%1,%2,%3},{%4,%5,%6,%7},{%8,%9},{%0,%1,%2,%3};"
        : "+f"(c[0]), "+f"(c[1]), "+f"(c[2]), "+f"(c[3])
        : "r"(a[0]), "r"(a[1]), "r"(a[2]), "r"(a[3]), "r"(b[0]), "r"(b[1]));
}

#define CP_ASYNC16(dst, src) \
    asm volatile("cp.async.cg.shared.global [%0], [%1], 16;" :: "r"(dst), "l"(src) : "memory")
#define CP_ASYNC4(dst, src) \
    asm volatile("cp.async.ca.shared.global [%0], [%1], 4;" :: "r"(dst), "l"(src) : "memory")
#define CP_COMMIT() asm volatile("cp.async.commit_group;" ::: "memory")
#define CP_WAIT1()  asm volatile("cp.async.wait_group 1;" ::: "memory")
#define CP_WAIT0()  asm volatile("cp.async.wait_group 0;" ::: "memory")

// ============================================================================
// fused tf32 rounding prepass: 3 activations (2^23 ea) + 4 weights (2^20 ea)
// ============================================================================
__global__ __launch_bounds__(256)
void round_all(const float* __restrict__ q, const float* __restrict__ k,
               const float* __restrict__ v, const float* __restrict__ wq,
               const float* __restrict__ wk, const float* __restrict__ wv,
               const float* __restrict__ wo)
{
    const size_t NAe = (size_t)MTOT * DMODEL;     // 2^23
    const size_t NWe = (size_t)DMODEL * DMODEL;   // 2^20
    size_t g = (((size_t)blockIdx.x * 256) + threadIdx.x) << 2;
    const float* src;
    float* dst;
    if (g < 3 * NAe) {
        int seg = (int)(g >> 23);
        size_t off = g & (NAe - 1);
        src = (seg == 0 ? q : (seg == 1 ? k : v)) + off;
        dst = g_ain[seg] + off;
    } else {
        size_t gw = g - 3 * NAe;
        int seg = (int)(gw >> 20);
        size_t off = gw & (NWe - 1);
        src = (seg == 0 ? wq : (seg == 1 ? wk : (seg == 2 ? wv : wo))) + off;
        dst = g_win[seg] + off;
    }
    float4 x = *(const float4*)src;
    x.x = __uint_as_float(f2tf(x.x));
    x.y = __uint_as_float(f2tf(x.y));
    x.z = __uint_as_float(f2tf(x.z));
    x.w = __uint_as_float(f2tf(x.w));
    *(float4*)dst = x;
}

// ============================================================================
// tf32 mma.sync GEMM-NT, pre-rounded inputs, 3-stage cp.async pipeline,
// ONE __syncthreads per K-iteration.
//   C[m,n] = sum_k A[m,k] * W[n,k] + bias[n]
//   mode 0: head-split out, tf32-rounded            (K, V)
//   mode 2: head-split out, tf32-rounded, x scaleQ  (Q)
//   mode 1: plain row-major out, full fp32          (final output)
// ============================================================================
#define GS 36
#define STG_FLTS (2 * 128 * GS)                  // floats per stage (A + W)
#define GEMM_SMEM (3 * STG_FLTS * 4)             // 110592 B
#define QSCALE (0.125f * 1.4426950408889634f)    // 1/sqrt(dk) * log2(e)

__device__ __forceinline__ void gemm_load_stage(uint32_t sbase,
                                                const float* __restrict__ Ag,
                                                const float* __restrict__ Wg,
                                                int s, int k0, int tid)
{
    const uint32_t stg = sbase + (uint32_t)(s * STG_FLTS * 4);
#pragma unroll
    for (int i = 0; i < 4; i++) {
        int idx = tid + 256 * i;
        int r   = idx >> 3;
        int c4  = (idx & 7) << 2;
        uint32_t d = (uint32_t)((r * GS + c4) * 4);
        CP_ASYNC16(stg + d,                    Ag + (size_t)r * DMODEL + k0 + c4);
        CP_ASYNC16(stg + 128 * GS * 4 + d,     Wg + (size_t)r * DMODEL + k0 + c4);
    }
}

__global__ __launch_bounds__(256)
void gemm_mma(const float* __restrict__ A, const float* __restrict__ W,
              const float* __restrict__ bias, float* __restrict__ C, int mode)
{
    extern __shared__ float sm[];
    const uint32_t sbase = smem_u32(sm);

    const int tid  = threadIdx.x;
    const int lane = tid & 31, wid = tid >> 5;
    const int wm = wid >> 2, wn = wid & 3;
    const int r0 = lane >> 2, c0 = lane & 3;

    const int rowBase = blockIdx.y * 128;
    const int colBase = blockIdx.x * 128;
    const float* Ag = A + (size_t)rowBase * DMODEL;
    const float* Wg = W + (size_t)colBase * DMODEL;

    float acc[4][4][4];
#pragma unroll
    for (int mf = 0; mf < 4; mf++)
#pragma unroll
        for (int nf = 0; nf < 4; nf++)
#pragma unroll
            for (int r = 0; r < 4; r++) acc[mf][nf][r] = 0.f;

    gemm_load_stage(sbase, Ag, Wg, 0, 0, tid);  CP_COMMIT();
    gemm_load_stage(sbase, Ag, Wg, 1, 32, tid); CP_COMMIT();

    const int NKT = DMODEL / 32;                 // 32
    int stg = 0;
    for (int kt = 0; kt < NKT; kt++) {
        CP_WAIT1();
        __syncthreads();
        // prefetch stage kt+2 into the buffer freed at the sync above
        if (kt + 2 < NKT) {
            int ps = stg + 2; if (ps >= 3) ps -= 3;
            gemm_load_stage(sbase, Ag, Wg, ps, (kt + 2) * 32, tid);
        }
        CP_COMMIT();                             // empty group when no load

        const float* as = sm + stg * STG_FLTS;
        const float* ws = as + 128 * GS;
#pragma unroll
        for (int ks = 0; ks < 4; ks++) {
            const int kc = ks * 8;
            uint32_t af[4][4], bf[4][2];
#pragma unroll
            for (int mf = 0; mf < 4; mf++) {
                const float* ap = as + (wm * 64 + mf * 16 + r0) * GS + kc + c0;
                af[mf][0] = __float_as_uint(ap[0]);
                af[mf][1] = __float_as_uint(ap[8 * GS]);
                af[mf][2] = __float_as_uint(ap[4]);
                af[mf][3] = __float_as_uint(ap[8 * GS + 4]);
            }
#pragma unroll
            for (int nf = 0; nf < 4; nf++) {
                const float* wp = ws + (wn * 32 + nf * 8 + r0) * GS + kc + c0;
                bf[nf][0] = __float_as_uint(wp[0]);
                bf[nf][1] = __float_as_uint(wp[4]);
            }
#pragma unroll
            for (int mf = 0; mf < 4; mf++)
#pragma unroll
                for (int nf = 0; nf < 4; nf++)
                    mma_tf32(acc[mf][nf], af[mf], bf[nf]);
        }
        if (++stg == 3) stg = 0;
    }

    const float oscale = (mode == 2) ? QSCALE : 1.0f;
#pragma unroll
    for (int mf = 0; mf < 4; mf++) {
        const int m0 = rowBase + wm * 64 + mf * 16 + r0;
        const int m1 = m0 + 8;
#pragma unroll
        for (int nf = 0; nf < 4; nf++) {
            const int n = colBase + wn * 32 + nf * 8 + 2 * c0;
            float2 v0, v1;
            v0.x = acc[mf][nf][0] + bias[n];
            v0.y = acc[mf][nf][1] + bias[n + 1];
            v1.x = acc[mf][nf][2] + bias[n];
            v1.y = acc[mf][nf][3] + bias[n + 1];
            if (mode == 1) {
                *(float2*)(C + (size_t)m0 * DMODEL + n) = v0;
                *(float2*)(C + (size_t)m1 * DMODEL + n) = v1;
            } else {
                v0.x = __uint_as_float(f2tf(v0.x * oscale));
                v0.y = __uint_as_float(f2tf(v0.y * oscale));
                v1.x = __uint_as_float(f2tf(v1.x * oscale));
                v1.y = __uint_as_float(f2tf(v1.y * oscale));
                const int hh = n >> 6, dd = n & 63;
                const int b0 = m0 >> 11, s0 = m0 & (SEQ - 1);
                const int b1 = m1 >> 11, s1 = m1 & (SEQ - 1);
                *(float2*)(C + ((((size_t)b0 * H_HEADS + hh) * SEQ + s0) << 6) + dd) = v0;
                *(float2*)(C + ((((size_t)b1 * H_HEADS + hh) * SEQ + s1) << 6) + dd) = v1;
            }
        }
    }
}

// ============================================================================
// Flash attention (exact R6 configuration — known good 475us):
//   q-tile 128, 4 warps (128 thr, bounds(128,2)), warp owns 32 q rows.
//   Q frags in regs; P via quad shuffles; K/V/mask double-buffered cp.async;
//   exp2-domain softmax.
// ============================================================================
#define QST 68
#define VST 72
#define ATT_SMEM ((2 * 64 * QST + 2 * 64 * VST) * 4 + 2 * 64 * 4)   // 72192 B

__device__ __forceinline__ void attn_fill(uint32_t kb, uint32_t vb, uint32_t mb,
                                          const float* __restrict__ Kg,
                                          const float* __restrict__ Vg,
                                          const int* __restrict__ mg,
                                          int kt, int tid)
{
#pragma unroll
    for (int i = 0; i < 8; i++) {
        int idx = tid + 128 * i;
        int r = idx >> 4, d4 = (idx & 15) << 2;
        CP_ASYNC16(kb + (uint32_t)((r * QST + d4) * 4),
                   Kg + ((size_t)kt * 64 + r) * 64 + d4);
        CP_ASYNC16(vb + (uint32_t)((r * VST + d4) * 4),
                   Vg + ((size_t)kt * 64 + r) * 64 + d4);
    }
    if (tid < 64) CP_ASYNC4(mb + (uint32_t)(tid * 4), mg + kt * 64 + tid);
}

__global__ __launch_bounds__(128, 2)
void attn_mma(const float* __restrict__ Q, const float* __restrict__ Kg_,
              const float* __restrict__ Vg_, const int* __restrict__ mask,
              float* __restrict__ ctx)
{
    extern __shared__ float sm[];
    float* Ks = sm;                               // [2][64][QST]
    float* Vs = sm + 2 * 64 * QST;                // [2][64][VST]
    int*   Ms = (int*)(sm + 2 * 64 * QST + 2 * 64 * VST);  // [2][64]

    const uint32_t sb  = smem_u32(sm);
    const uint32_t KsB = sb;
    const uint32_t VsB = sb + 2 * 64 * QST * 4;
    const uint32_t MsB = sb + (2 * 64 * QST + 2 * 64 * VST) * 4;

    const int tid  = threadIdx.x;
    const int lane = tid & 31, wid = tid >> 5;
    const int r0 = lane >> 2, c0 = lane & 3;
    const int qt = blockIdx.x, h = blockIdx.y, b = blockIdx.z;

    const size_t bh = (size_t)b * H_HEADS + h;
    const float* Qg = Q   + (bh * SEQ + (size_t)qt * 128) * 64;
    const float* Kg = Kg_ + bh * SEQ * 64;
    const float* Vg = Vg_ + bh * SEQ * 64;
    const int*   mg = mask + (size_t)b * SEQ;

    uint32_t qa[2][8][4];
    {
        const float* Qw = Qg + (size_t)(wid * 32) * 64;
#pragma unroll
        for (int mf = 0; mf < 2; mf++)
#pragma unroll
            for (int ks = 0; ks < 8; ks++) {
                const int kc = ks * 8;
                const float* p = Qw + (size_t)(mf * 16 + r0) * 64 + kc + c0;
                qa[mf][ks][0] = __float_as_uint(p[0]);
                qa[mf][ks][1] = __float_as_uint(p[8 * 64]);
                qa[mf][ks][2] = __float_as_uint(p[4]);
                qa[mf][ks][3] = __float_as_uint(p[8 * 64 + 4]);
            }
    }

    float o[2][8][4];
#pragma unroll
    for (int mf = 0; mf < 2; mf++)
#pragma unroll
        for (int df = 0; df < 8; df++)
#pragma unroll
            for (int r = 0; r < 4; r++) o[mf][df][r] = 0.f;

    float mprev[2][2], lsum[2][2];
#pragma unroll
    for (int mf = 0; mf < 2; mf++) {
        mprev[mf][0] = -1e30f; mprev[mf][1] = -1e30f;
        lsum[mf][0] = 0.f;     lsum[mf][1] = 0.f;
    }

    const int Lq  = (lane & 28) | (c0 >> 1);
    const int Lq2 = Lq | 2;
    const bool oddc = (c0 & 1) != 0;

    attn_fill(KsB, VsB, MsB, Kg, Vg, mg, 0, tid);
    CP_COMMIT();

    const int nkt = SEQ / 64;
    for (int kt = 0; kt < nkt; kt++) {
        CP_WAIT0();
        __syncthreads();

        const int cur = kt & 1;
        if (kt + 1 < nkt) {
            const int nxt = (kt + 1) & 1;
            attn_fill(KsB + (uint32_t)(nxt * 64 * QST * 4),
                      VsB + (uint32_t)(nxt * 64 * VST * 4),
                      MsB + (uint32_t)(nxt * 256),
                      Kg, Vg, mg, kt + 1, tid);
        }
        CP_COMMIT();

        const float* ks_ = Ks + cur * 64 * QST;
        const float* vs_ = Vs + cur * 64 * VST;
        const int*   ms_ = Ms + cur * 64;

        float s[2][8][4];
#pragma unroll
        for (int mf = 0; mf < 2; mf++)
#pragma unroll
            for (int nf = 0; nf < 8; nf++)
#pragma unroll
                for (int r = 0; r < 4; r++) s[mf][nf][r] = 0.f;

#pragma unroll
        for (int ks = 0; ks < 8; ks++) {
            const int kc = ks * 8;
#pragma unroll
            for (int nf = 0; nf < 8; nf++) {
                uint32_t bb[2];
                const float* bp = ks_ + (nf * 8 + r0) * QST + kc + c0;
                bb[0] = __float_as_uint(bp[0]);
                bb[1] = __float_as_uint(bp[4]);
                mma_tf32(s[0][nf], qa[0][ks], bb);
                mma_tf32(s[1][nf], qa[1][ks], bb);
            }
        }

#pragma unroll
        for (int nf = 0; nf < 8; nf++) {
            const int nc = nf * 8 + 2 * c0;
            const bool k0m = ms_[nc] != 0, k1m = ms_[nc + 1] != 0;
#pragma unroll
            for (int mf = 0; mf < 2; mf++) {
                s[mf][nf][0] = k0m ? s[mf][nf][0] : -1e9f;
                s[mf][nf][1] = k1m ? s[mf][nf][1] : -1e9f;
                s[mf][nf][2] = k0m ? s[mf][nf][2] : -1e9f;
                s[mf][nf][3] = k1m ? s[mf][nf][3] : -1e9f;
            }
        }

#pragma unroll
        for (int mf = 0; mf < 2; mf++) {
            float rmax0 = -1e30f, rmax1 = -1e30f;
#pragma unroll
            for (int nf = 0; nf < 8; nf++) {
                rmax0 = fmaxf(rmax0, fmaxf(s[mf][nf][0], s[mf][nf][1]));
                rmax1 = fmaxf(rmax1, fmaxf(s[mf][nf][2], s[mf][nf][3]));
            }
            rmax0 = fmaxf(rmax0, __shfl_xor_sync(0xffffffffu, rmax0, 1));
            rmax0 = fmaxf(rmax0, __shfl_xor_sync(0xffffffffu, rmax0, 2));
            rmax1 = fmaxf(rmax1, __shfl_xor_sync(0xffffffffu, rmax1, 1));
            rmax1 = fmaxf(rmax1, __shfl_xor_sync(0xffffffffu, rmax1, 2));

            const float mn0 = fmaxf(mprev[mf][0], rmax0);
            const float mn1 = fmaxf(mprev[mf][1], rmax1);
            const float fac0 = ex2(mprev[mf][0] - mn0);
            const float fac1 = ex2(mprev[mf][1] - mn1);

            float rs0 = 0.f, rs1 = 0.f;
#pragma unroll
            for (int nf = 0; nf < 8; nf++) {
                s[mf][nf][0] = ex2(s[mf][nf][0] - mn0);
                s[mf][nf][1] = ex2(s[mf][nf][1] - mn0);
                s[mf][nf][2] = ex2(s[mf][nf][2] - mn1);
                s[mf][nf][3] = ex2(s[mf][nf][3] - mn1);
                rs0 += s[mf][nf][0] + s[mf][nf][1];
                rs1 += s[mf][nf][2] + s[mf][nf][3];
            }
            rs0 += __shfl_xor_sync(0xffffffffu, rs0, 1);
            rs0 += __shfl_xor_sync(0xffffffffu, rs0, 2);
            rs1 += __shfl_xor_sync(0xffffffffu, rs1, 1);
            rs1 += __shfl_xor_sync(0xffffffffu, rs1, 2);

            lsum[mf][0] = lsum[mf][0] * fac0 + rs0;
            lsum[mf][1] = lsum[mf][1] * fac1 + rs1;
            mprev[mf][0] = mn0; mprev[mf][1] = mn1;
#pragma unroll
            for (int df = 0; df < 8; df++) {
                o[mf][df][0] *= fac0; o[mf][df][1] *= fac0;
                o[mf][df][2] *= fac1; o[mf][df][3] *= fac1;
            }
        }

#pragma unroll
        for (int ks = 0; ks < 8; ks++) {
            const int kc = ks * 8;
            uint32_t a0[4], a1[4];
#pragma unroll
            for (int mf = 0; mf < 2; mf++) {
                float t0 = __shfl_sync(0xffffffffu, s[mf][ks][0], Lq);
                float t1 = __shfl_sync(0xffffffffu, s[mf][ks][1], Lq);
                float t2 = __shfl_sync(0xffffffffu, s[mf][ks][2], Lq);
                float t3 = __shfl_sync(0xffffffffu, s[mf][ks][3], Lq);
                float u0 = __shfl_sync(0xffffffffu, s[mf][ks][0], Lq2);
                float u1 = __shfl_sync(0xffffffffu, s[mf][ks][1], Lq2);
                float u2 = __shfl_sync(0xffffffffu, s[mf][ks][2], Lq2);
                float u3 = __shfl_sync(0xffffffffu, s[mf][ks][3], Lq2);
                uint32_t* a = mf ? a1 : a0;
                a[0] = f2tf(oddc ? t1 : t0);
                a[1] = f2tf(oddc ? t3 : t2);
                a[2] = f2tf(oddc ? u1 : u0);
                a[3] = f2tf(oddc ? u3 : u2);
            }
#pragma unroll
            for (int df = 0; df < 8; df++) {
                uint32_t bb[2];
                const float* vp = vs_ + (kc + c0) * VST + df * 8 + r0;
                bb[0] = __float_as_uint(vp[0]);
                bb[1] = __float_as_uint(vp[4 * VST]);
                mma_tf32(o[0][df], a0, bb);
                mma_tf32(o[1][df], a1, bb);
            }
        }
    }

#pragma unroll
    for (int mf = 0; mf < 2; mf++) {
        const float inv0 = (lsum[mf][0] > 0.f) ? (1.f / lsum[mf][0]) : 0.f;
        const float inv1 = (lsum[mf][1] > 0.f) ? (1.f / lsum[mf][1]) : 0.f;
        const int q0 = qt * 128 + wid * 32 + mf * 16 + r0;
#pragma unroll
        for (int df = 0; df < 8; df++) {
            const int d = df * 8 + 2 * c0;
            float2 v0, v1;
            v0.x = __uint_as_float(f2tf(o[mf][df][0] * inv0));
            v0.y = __uint_as_float(f2tf(o[mf][df][1] * inv0));
            v1.x = __uint_as_float(f2tf(o[mf][df][2] * inv1));
            v1.y = __uint_as_float(f2tf(o[mf][df][3] * inv1));
            *(float2*)(ctx + ((size_t)(b * SEQ + q0) * H_HEADS + h) * 64 + d) = v0;
            *(float2*)(ctx + ((size_t)(b * SEQ + q0 + 8) * H_HEADS + h) * 64 + d) = v1;
        }
    }
}

// ============================================================================
// launch
// ============================================================================
extern "C" void kernel_launch(void* const* d_in, const int* in_sizes, int n_in,
                              void* d_out, int out_size)
{
    const float* query = (const float*)d_in[0];
    const float* key_  = (const float*)d_in[1];
    const float* value = (const float*)d_in[2];
    const int*   mask  = (const int*)  d_in[3];
    const float* Wq = (const float*)d_in[4];
    const float* bq = (const float*)d_in[5];
    const float* Wk = (const float*)d_in[6];
    const float* bk = (const float*)d_in[7];
    const float* Wv = (const float*)d_in[8];
    const float* bv = (const float*)d_in[9];
    const float* Wo = (const float*)d_in[10];
    const float* bo = (const float*)d_in[11];
    float* out = (float*)d_out;

    float *gq, *gk, *gv, *gctx, *gain, *gwin;
    cudaGetSymbolAddress((void**)&gq,   g_q);
    cudaGetSymbolAddress((void**)&gk,   g_k);
    cudaGetSymbolAddress((void**)&gv,   g_v);
    cudaGetSymbolAddress((void**)&gctx, g_ctx);
    cudaGetSymbolAddress((void**)&gain, g_ain);
    cudaGetSymbolAddress((void**)&gwin, g_win);

    float* aq = gain;
    float* ak = gain + (size_t)MTOT * DMODEL;
    float* av = gain + 2 * (size_t)MTOT * DMODEL;
    float* wq = gwin;
    float* wk = gwin + (size_t)DMODEL * DMODEL;
    float* wv = gwin + 2 * (size_t)DMODEL * DMODEL;
    float* wo = gwin + 3 * (size_t)DMODEL * DMODEL;

    cudaFuncSetAttribute(gemm_mma,
                         cudaFuncAttributeMaxDynamicSharedMemorySize, GEMM_SMEM);
    cudaFuncSetAttribute(attn_mma,
                         cudaFuncAttributeMaxDynamicSharedMemorySize, ATT_SMEM);

    // ---- fused prepass: tf32-round all activations and weights ----
    const size_t NA = (size_t)MTOT * DMODEL;      // 2^23
    const size_t NW = (size_t)DMODEL * DMODEL;    // 2^20
    const int nblk = (int)((3 * NA + 4 * NW) / 1024);   // 28672
    round_all<<<nblk, 256>>>(query, key_, value, Wq, Wk, Wv, Wo);

    const int M = MTOT;                           // 8192
    dim3 ggrid(DMODEL / 128, M / 128);            // (8, 64)
    dim3 gblock(256);

    gemm_mma<<<ggrid, gblock, GEMM_SMEM>>>(aq, wq, bq, gq, 2);  // Q: tf32, *0.125*log2e
    gemm_mma<<<ggrid, gblock, GEMM_SMEM>>>(ak, wk, bk, gk, 0);  // K: tf32
    gemm_mma<<<ggrid, gblock, GEMM_SMEM>>>(av, wv, bv, gv, 0);  // V: tf32

    dim3 agrid(SEQ / 128, H_HEADS, BATCH);        // (16, 16, 4)
    attn_mma<<<agrid, dim3(128), ATT_SMEM>>>(gq, gk, gv, mask, gctx);

    gemm_mma<<<ggrid, gblock, GEMM_SMEM>>>(gctx, wo, bo, out, 1);
}

// round 9
// speedup vs baseline: 1.3432x; 1.3432x over previous
#include <cuda_runtime.h>
#include <cstdint>

// ---------------- problem constants ----------------
#define H_HEADS 16
#define DMODEL  1024
#define BATCH   4
#define SEQ     2048
#define MTOT    (BATCH * SEQ)          // 8192

// ---------------- scratch (static device globals; no allocs) ----------------
__device__ float g_q[(size_t)BATCH * H_HEADS * SEQ * 64];   // tf32, pre-scaled 0.125*log2e
__device__ float g_k[(size_t)BATCH * H_HEADS * SEQ * 64];   // tf32
__device__ float g_v[(size_t)BATCH * H_HEADS * SEQ * 64];   // tf32
__device__ float g_ctx[(size_t)BATCH * SEQ * DMODEL];       // tf32-rounded (B,S,H*dk)
__device__ float g_ain[3][(size_t)MTOT * DMODEL];           // tf32 copies of q/k/v inputs
__device__ float g_win[4][(size_t)DMODEL * DMODEL];         // tf32 copies of Wq/Wk/Wv/Wo

// ---------------- helpers ----------------
__device__ __forceinline__ uint32_t smem_u32(const void* p) {
    uint32_t a;
    asm("{ .reg .u64 t; cvta.to.shared.u64 t, %1; cvt.u32.u64 %0, t; }"
        : "=r"(a) : "l"(p));
    return a;
}

__device__ __forceinline__ uint32_t f2tf(float x) {
    uint32_t r;
    asm("cvt.rna.tf32.f32 %0, %1;" : "=r"(r) : "f"(x));
    return r;
}

__device__ __forceinline__ float ex2(float x) {
    float y;
    asm("ex2.approx.f32 %0, %1;" : "=f"(y) : "f"(x));
    return y;
}

// D += A(m16k8, tf32) * B(k8n8, tf32)   (row.col)
__device__ __forceinline__ void mma_tf32(float* c, const uint32_t* a, const uint32_t* b) {
    asm volatile(
        "mma.sync.aligned.m16n8k8.row.col.f32.tf32.tf32.f32 "
        "{%0,%1,%2,%3},{%4,%5,%6,%7},{%8,%9},{%0,%1,%2,%3};"
        : "+f"(c[0]), "+f"(c[1]), "+f"(c[2]), "+f"(c[3])
        : "r"(a[0]), "r"(a[1]), "r"(a[2]), "r"(a[3]), "r"(b[0]), "r"(b[1]));
}

#define CP_ASYNC16(dst, src) \
    asm volatile("cp.async.cg.shared.global [%0], [%1], 16;" :: "r"(dst), "l"(src) : "memory")
#define CP_ASYNC4(dst, src) \
    asm volatile("cp.async.ca.shared.global [%0], [%1], 4;" :: "r"(dst), "l"(src) : "memory")
#define CP_COMMIT() asm volatile("cp.async.commit_group;" ::: "memory")
#define CP_WAIT1()  asm volatile("cp.async.wait_group 1;" ::: "memory")
#define CP_WAIT0()  asm volatile("cp.async.wait_group 0;" ::: "memory")

// ============================================================================
// fused tf32 rounding prepass: 3 activations (2^23 ea) + 4 weights (2^20 ea)
// ============================================================================
__global__ __launch_bounds__(256)
void round_all(const float* __restrict__ q, const float* __restrict__ k,
               const float* __restrict__ v, const float* __restrict__ wq,
               const float* __restrict__ wk, const float* __restrict__ wv,
               const float* __restrict__ wo)
{
    const size_t NAe = (size_t)MTOT * DMODEL;     // 2^23
    const size_t NWe = (size_t)DMODEL * DMODEL;   // 2^20
    size_t g = (((size_t)blockIdx.x * 256) + threadIdx.x) << 2;
    const float* src;
    float* dst;
    if (g < 3 * NAe) {
        int seg = (int)(g >> 23);
        size_t off = g & (NAe - 1);
        src = (seg == 0 ? q : (seg == 1 ? k : v)) + off;
        dst = g_ain[seg] + off;
    } else {
        size_t gw = g - 3 * NAe;
        int seg = (int)(gw >> 20);
        size_t off = gw & (NWe - 1);
        src = (seg == 0 ? wq : (seg == 1 ? wk : (seg == 2 ? wv : wo))) + off;
        dst = g_win[seg] + off;
    }
    float4 x = *(const float4*)src;
    x.x = __uint_as_float(f2tf(x.x));
    x.y = __uint_as_float(f2tf(x.y));
    x.z = __uint_as_float(f2tf(x.z));
    x.w = __uint_as_float(f2tf(x.w));
    *(float4*)dst = x;
}

// ============================================================================
// tf32 mma.sync GEMM-NT body (exact R6 pipeline: double buffer, 2 syncs/iter)
//   C[m,n] = sum_k A[m,k] * W[n,k] + bias[n]
//   mode 0: head-split out, tf32-rounded            (K, V)
//   mode 2: head-split out, tf32-rounded, x scaleQ  (Q)
//   mode 1: plain row-major out, full fp32          (final output)
// ============================================================================
#define GS 36
#define GEMM_SMEM (2 * 2 * 128 * GS * 4)        // 73728 B
#define QSCALE (0.125f * 1.4426950408889634f)   // 1/sqrt(dk) * log2(e)

__device__ __forceinline__ void gemm_load_stage(uint32_t sbase, uint32_t woffB,
                                                const float* __restrict__ Ag,
                                                const float* __restrict__ Wg,
                                                int s, int k0, int tid)
{
#pragma unroll
    for (int i = 0; i < 4; i++) {
        int idx = tid + 256 * i;
        int r   = idx >> 3;
        int c4  = (idx & 7) << 2;
        uint32_t d = (uint32_t)(((s * 128 + r) * GS + c4) * 4);
        CP_ASYNC16(sbase + d,         Ag + (size_t)r * DMODEL + k0 + c4);
        CP_ASYNC16(sbase + woffB + d, Wg + (size_t)r * DMODEL + k0 + c4);
    }
}

__device__ __forceinline__ void gemm_body(const float* __restrict__ A,
                                          const float* __restrict__ W,
                                          const float* __restrict__ bias,
                                          float* __restrict__ C, int mode,
                                          int bx, int by)
{
    extern __shared__ float sm[];
    const float* As  = sm;
    const float* Ws_ = sm + 2 * 128 * GS;
    const uint32_t sbase = smem_u32(sm);
    const uint32_t woffB = (uint32_t)(2 * 128 * GS * 4);

    const int tid  = threadIdx.x;
    const int lane = tid & 31, wid = tid >> 5;
    const int wm = wid >> 2, wn = wid & 3;
    const int r0 = lane >> 2, c0 = lane & 3;

    const int rowBase = by * 128;
    const int colBase = bx * 128;
    const float* Ag = A + (size_t)rowBase * DMODEL;
    const float* Wg = W + (size_t)colBase * DMODEL;

    float acc[4][4][4];
#pragma unroll
    for (int mf = 0; mf < 4; mf++)
#pragma unroll
        for (int nf = 0; nf < 4; nf++)
#pragma unroll
            for (int r = 0; r < 4; r++) acc[mf][nf][r] = 0.f;

    gemm_load_stage(sbase, woffB, Ag, Wg, 0, 0, tid);  CP_COMMIT();
    gemm_load_stage(sbase, woffB, Ag, Wg, 1, 32, tid); CP_COMMIT();

    for (int kt = 0; kt < DMODEL / 32; kt++) {
        CP_WAIT1();
        __syncthreads();
        const float* as = As  + (kt & 1) * 128 * GS;
        const float* ws = Ws_ + (kt & 1) * 128 * GS;
#pragma unroll
        for (int ks = 0; ks < 4; ks++) {
            const int kc = ks * 8;
            uint32_t af[4][4], bf[4][2];
#pragma unroll
            for (int mf = 0; mf < 4; mf++) {
                const float* ap = as + (wm * 64 + mf * 16 + r0) * GS + kc + c0;
                af[mf][0] = __float_as_uint(ap[0]);
                af[mf][1] = __float_as_uint(ap[8 * GS]);
                af[mf][2] = __float_as_uint(ap[4]);
                af[mf][3] = __float_as_uint(ap[8 * GS + 4]);
            }
#pragma unroll
            for (int nf = 0; nf < 4; nf++) {
                const float* wp = ws + (wn * 32 + nf * 8 + r0) * GS + kc + c0;
                bf[nf][0] = __float_as_uint(wp[0]);
                bf[nf][1] = __float_as_uint(wp[4]);
            }
#pragma unroll
            for (int mf = 0; mf < 4; mf++)
#pragma unroll
                for (int nf = 0; nf < 4; nf++)
                    mma_tf32(acc[mf][nf], af[mf], bf[nf]);
        }
        __syncthreads();
        if (kt + 2 < DMODEL / 32)
            gemm_load_stage(sbase, woffB, Ag, Wg, kt & 1, (kt + 2) * 32, tid);
        CP_COMMIT();
    }

    const float oscale = (mode == 2) ? QSCALE : 1.0f;
#pragma unroll
    for (int mf = 0; mf < 4; mf++) {
        const int m0 = rowBase + wm * 64 + mf * 16 + r0;
        const int m1 = m0 + 8;
#pragma unroll
        for (int nf = 0; nf < 4; nf++) {
            const int n = colBase + wn * 32 + nf * 8 + 2 * c0;
            float2 v0, v1;
            v0.x = acc[mf][nf][0] + bias[n];
            v0.y = acc[mf][nf][1] + bias[n + 1];
            v1.x = acc[mf][nf][2] + bias[n];
            v1.y = acc[mf][nf][3] + bias[n + 1];
            if (mode == 1) {
                *(float2*)(C + (size_t)m0 * DMODEL + n) = v0;
                *(float2*)(C + (size_t)m1 * DMODEL + n) = v1;
            } else {
                v0.x = __uint_as_float(f2tf(v0.x * oscale));
                v0.y = __uint_as_float(f2tf(v0.y * oscale));
                v1.x = __uint_as_float(f2tf(v1.x * oscale));
                v1.y = __uint_as_float(f2tf(v1.y * oscale));
                const int hh = n >> 6, dd = n & 63;
                const int b0 = m0 >> 11, s0 = m0 & (SEQ - 1);
                const int b1 = m1 >> 11, s1 = m1 & (SEQ - 1);
                *(float2*)(C + ((((size_t)b0 * H_HEADS + hh) * SEQ + s0) << 6) + dd) = v0;
                *(float2*)(C + ((((size_t)b1 * H_HEADS + hh) * SEQ + s1) << 6) + dd) = v1;
            }
        }
    }
}

// single GEMM (output projection)
__global__ __launch_bounds__(256)
void gemm_mma(const float* __restrict__ A, const float* __restrict__ W,
              const float* __restrict__ bias, float* __restrict__ C, int mode)
{
    gemm_body(A, W, bias, C, mode, blockIdx.x, blockIdx.y);
}

// fused Q/K/V projections: blockIdx.z selects the problem (1536 CTAs/launch)
__global__ __launch_bounds__(256)
void gemm_qkv(const float* __restrict__ aq, const float* __restrict__ ak,
              const float* __restrict__ av, const float* __restrict__ wq,
              const float* __restrict__ wk, const float* __restrict__ wv,
              const float* __restrict__ bq, const float* __restrict__ bk,
              const float* __restrict__ bv, float* __restrict__ cq,
              float* __restrict__ ck, float* __restrict__ cv)
{
    const int z = blockIdx.z;
    const float* A    = (z == 0) ? aq : ((z == 1) ? ak : av);
    const float* W    = (z == 0) ? wq : ((z == 1) ? wk : wv);
    const float* bias = (z == 0) ? bq : ((z == 1) ? bk : bv);
    float*       C    = (z == 0) ? cq : ((z == 1) ? ck : cv);
    gemm_body(A, W, bias, C, (z == 0) ? 2 : 0, blockIdx.x, blockIdx.y);
}

// ============================================================================
// Flash attention (exact R6 configuration — known good):
//   q-tile 128, 4 warps (128 thr, bounds(128,2)), warp owns 32 q rows.
//   Q frags in regs; P via quad shuffles; K/V/mask double-buffered cp.async;
//   exp2-domain softmax.
// ============================================================================
#define QST 68
#define VST 72
#define ATT_SMEM ((2 * 64 * QST + 2 * 64 * VST) * 4 + 2 * 64 * 4)   // 72192 B

__device__ __forceinline__ void attn_fill(uint32_t kb, uint32_t vb, uint32_t mb,
                                          const float* __restrict__ Kg,
                                          const float* __restrict__ Vg,
                                          const int* __restrict__ mg,
                                          int kt, int tid)
{
#pragma unroll
    for (int i = 0; i < 8; i++) {
        int idx = tid + 128 * i;
        int r = idx >> 4, d4 = (idx & 15) << 2;
        CP_ASYNC16(kb + (uint32_t)((r * QST + d4) * 4),
                   Kg + ((size_t)kt * 64 + r) * 64 + d4);
        CP_ASYNC16(vb + (uint32_t)((r * VST + d4) * 4),
                   Vg + ((size_t)kt * 64 + r) * 64 + d4);
    }
    if (tid < 64) CP_ASYNC4(mb + (uint32_t)(tid * 4), mg + kt * 64 + tid);
}

__global__ __launch_bounds__(128, 2)
void attn_mma(const float* __restrict__ Q, const float* __restrict__ Kg_,
              const float* __restrict__ Vg_, const int* __restrict__ mask,
              float* __restrict__ ctx)
{
    extern __shared__ float sm[];
    float* Ks = sm;                               // [2][64][QST]
    float* Vs = sm + 2 * 64 * QST;                // [2][64][VST]
    int*   Ms = (int*)(sm + 2 * 64 * QST + 2 * 64 * VST);  // [2][64]

    const uint32_t sb  = smem_u32(sm);
    const uint32_t KsB = sb;
    const uint32_t VsB = sb + 2 * 64 * QST * 4;
    const uint32_t MsB = sb + (2 * 64 * QST + 2 * 64 * VST) * 4;

    const int tid  = threadIdx.x;
    const int lane = tid & 31, wid = tid >> 5;
    const int r0 = lane >> 2, c0 = lane & 3;
    const int qt = blockIdx.x, h = blockIdx.y, b = blockIdx.z;

    const size_t bh = (size_t)b * H_HEADS + h;
    const float* Qg = Q   + (bh * SEQ + (size_t)qt * 128) * 64;
    const float* Kg = Kg_ + bh * SEQ * 64;
    const float* Vg = Vg_ + bh * SEQ * 64;
    const int*   mg = mask + (size_t)b * SEQ;

    uint32_t qa[2][8][4];
    {
        const float* Qw = Qg + (size_t)(wid * 32) * 64;
#pragma unroll
        for (int mf = 0; mf < 2; mf++)
#pragma unroll
            for (int ks = 0; ks < 8; ks++) {
                const int kc = ks * 8;
                const float* p = Qw + (size_t)(mf * 16 + r0) * 64 + kc + c0;
                qa[mf][ks][0] = __float_as_uint(p[0]);
                qa[mf][ks][1] = __float_as_uint(p[8 * 64]);
                qa[mf][ks][2] = __float_as_uint(p[4]);
                qa[mf][ks][3] = __float_as_uint(p[8 * 64 + 4]);
            }
    }

    float o[2][8][4];
#pragma unroll
    for (int mf = 0; mf < 2; mf++)
#pragma unroll
        for (int df = 0; df < 8; df++)
#pragma unroll
            for (int r = 0; r < 4; r++) o[mf][df][r] = 0.f;

    float mprev[2][2], lsum[2][2];
#pragma unroll
    for (int mf = 0; mf < 2; mf++) {
        mprev[mf][0] = -1e30f; mprev[mf][1] = -1e30f;
        lsum[mf][0] = 0.f;     lsum[mf][1] = 0.f;
    }

    const int Lq  = (lane & 28) | (c0 >> 1);
    const int Lq2 = Lq | 2;
    const bool oddc = (c0 & 1) != 0;

    attn_fill(KsB, VsB, MsB, Kg, Vg, mg, 0, tid);
    CP_COMMIT();

    const int nkt = SEQ / 64;
    for (int kt = 0; kt < nkt; kt++) {
        CP_WAIT0();
        __syncthreads();

        const int cur = kt & 1;
        if (kt + 1 < nkt) {
            const int nxt = (kt + 1) & 1;
            attn_fill(KsB + (uint32_t)(nxt * 64 * QST * 4),
                      VsB + (uint32_t)(nxt * 64 * VST * 4),
                      MsB + (uint32_t)(nxt * 256),
                      Kg, Vg, mg, kt + 1, tid);
        }
        CP_COMMIT();

        const float* ks_ = Ks + cur * 64 * QST;
        const float* vs_ = Vs + cur * 64 * VST;
        const int*   ms_ = Ms + cur * 64;

        float s[2][8][4];
#pragma unroll
        for (int mf = 0; mf < 2; mf++)
#pragma unroll
            for (int nf = 0; nf < 8; nf++)
#pragma unroll
                for (int r = 0; r < 4; r++) s[mf][nf][r] = 0.f;

#pragma unroll
        for (int ks = 0; ks < 8; ks++) {
            const int kc = ks * 8;
#pragma unroll
            for (int nf = 0; nf < 8; nf++) {
                uint32_t bb[2];
                const float* bp = ks_ + (nf * 8 + r0) * QST + kc + c0;
                bb[0] = __float_as_uint(bp[0]);
                bb[1] = __float_as_uint(bp[4]);
                mma_tf32(s[0][nf], qa[0][ks], bb);
                mma_tf32(s[1][nf], qa[1][ks], bb);
            }
        }

#pragma unroll
        for (int nf = 0; nf < 8; nf++) {
            const int nc = nf * 8 + 2 * c0;
            const bool k0m = ms_[nc] != 0, k1m = ms_[nc + 1] != 0;
#pragma unroll
            for (int mf = 0; mf < 2; mf++) {
                s[mf][nf][0] = k0m ? s[mf][nf][0] : -1e9f;
                s[mf][nf][1] = k1m ? s[mf][nf][1] : -1e9f;
                s[mf][nf][2] = k0m ? s[mf][nf][2] : -1e9f;
                s[mf][nf][3] = k1m ? s[mf][nf][3] : -1e9f;
            }
        }

#pragma unroll
        for (int mf = 0; mf < 2; mf++) {
            float rmax0 = -1e30f, rmax1 = -1e30f;
#pragma unroll
            for (int nf = 0; nf < 8; nf++) {
                rmax0 = fmaxf(rmax0, fmaxf(s[mf][nf][0], s[mf][nf][1]));
                rmax1 = fmaxf(rmax1, fmaxf(s[mf][nf][2], s[mf][nf][3]));
            }
            rmax0 = fmaxf(rmax0, __shfl_xor_sync(0xffffffffu, rmax0, 1));
            rmax0 = fmaxf(rmax0, __shfl_xor_sync(0xffffffffu, rmax0, 2));
            rmax1 = fmaxf(rmax1, __shfl_xor_sync(0xffffffffu, rmax1, 1));
            rmax1 = fmaxf(rmax1, __shfl_xor_sync(0xffffffffu, rmax1, 2));

            const float mn0 = fmaxf(mprev[mf][0], rmax0);
            const float mn1 = fmaxf(mprev[mf][1], rmax1);
            const float fac0 = ex2(mprev[mf][0] - mn0);
            const float fac1 = ex2(mprev[mf][1] - mn1);

            float rs0 = 0.f, rs1 = 0.f;
#pragma unroll
            for (int nf = 0; nf < 8; nf++) {
                s[mf][nf][0] = ex2(s[mf][nf][0] - mn0);
                s[mf][nf][1] = ex2(s[mf][nf][1] - mn0);
                s[mf][nf][2] = ex2(s[mf][nf][2] - mn1);
                s[mf][nf][3] = ex2(s[mf][nf][3] - mn1);
                rs0 += s[mf][nf][0] + s[mf][nf][1];
                rs1 += s[mf][nf][2] + s[mf][nf][3];
            }
            rs0 += __shfl_xor_sync(0xffffffffu, rs0, 1);
            rs0 += __shfl_xor_sync(0xffffffffu, rs0, 2);
            rs1 += __shfl_xor_sync(0xffffffffu, rs1, 1);
            rs1 += __shfl_xor_sync(0xffffffffu, rs1, 2);

            lsum[mf][0] = lsum[mf][0] * fac0 + rs0;
            lsum[mf][1] = lsum[mf][1] * fac1 + rs1;
            mprev[mf][0] = mn0; mprev[mf][1] = mn1;
#pragma unroll
            for (int df = 0; df < 8; df++) {
                o[mf][df][0] *= fac0; o[mf][df][1] *= fac0;
                o[mf][df][2] *= fac1; o[mf][df][3] *= fac1;
            }
        }

#pragma unroll
        for (int ks = 0; ks < 8; ks++) {
            const int kc = ks * 8;
            uint32_t a0[4], a1[4];
#pragma unroll
            for (int mf = 0; mf < 2; mf++) {
                float t0 = __shfl_sync(0xffffffffu, s[mf][ks][0], Lq);
                float t1 = __shfl_sync(0xffffffffu, s[mf][ks][1], Lq);
                float t2 = __shfl_sync(0xffffffffu, s[mf][ks][2], Lq);
                float t3 = __shfl_sync(0xffffffffu, s[mf][ks][3], Lq);
                float u0 = __shfl_sync(0xffffffffu, s[mf][ks][0], Lq2);
                float u1 = __shfl_sync(0xffffffffu, s[mf][ks][1], Lq2);
                float u2 = __shfl_sync(0xffffffffu, s[mf][ks][2], Lq2);
                float u3 = __shfl_sync(0xffffffffu, s[mf][ks][3], Lq2);
                uint32_t* a = mf ? a1 : a0;
                a[0] = f2tf(oddc ? t1 : t0);
                a[1] = f2tf(oddc ? t3 : t2);
                a[2] = f2tf(oddc ? u1 : u0);
                a[3] = f2tf(oddc ? u3 : u2);
            }
#pragma unroll
            for (int df = 0; df < 8; df++) {
                uint32_t bb[2];
                const float* vp = vs_ + (kc + c0) * VST + df * 8 + r0;
                bb[0] = __float_as_uint(vp[0]);
                bb[1] = __float_as_uint(vp[4 * VST]);
                mma_tf32(o[0][df], a0, bb);
                mma_tf32(o[1][df], a1, bb);
            }
        }
    }

#pragma unroll
    for (int mf = 0; mf < 2; mf++) {
        const float inv0 = (lsum[mf][0] > 0.f) ? (1.f / lsum[mf][0]) : 0.f;
        const float inv1 = (lsum[mf][1] > 0.f) ? (1.f / lsum[mf][1]) : 0.f;
        const int q0 = qt * 128 + wid * 32 + mf * 16 + r0;
#pragma unroll
        for (int df = 0; df < 8; df++) {
            const int d = df * 8 + 2 * c0;
            float2 v0, v1;
            v0.x = __uint_as_float(f2tf(o[mf][df][0] * inv0));
            v0.y = __uint_as_float(f2tf(o[mf][df][1] * inv0));
            v1.x = __uint_as_float(f2tf(o[mf][df][2] * inv1));
            v1.y = __uint_as_float(f2tf(o[mf][df][3] * inv1));
            *(float2*)(ctx + ((size_t)(b * SEQ + q0) * H_HEADS + h) * 64 + d) = v0;
            *(float2*)(ctx + ((size_t)(b * SEQ + q0 + 8) * H_HEADS + h) * 64 + d) = v1;
        }
    }
}

// ============================================================================
// launch
// ============================================================================
extern "C" void kernel_launch(void* const* d_in, const int* in_sizes, int n_in,
                              void* d_out, int out_size)
{
    const float* query = (const float*)d_in[0];
    const float* key_  = (const float*)d_in[1];
    const float* value = (const float*)d_in[2];
    const int*   mask  = (const int*)  d_in[3];
    const float* Wq = (const float*)d_in[4];
    const float* bq = (const float*)d_in[5];
    const float* Wk = (const float*)d_in[6];
    const float* bk = (const float*)d_in[7];
    const float* Wv = (const float*)d_in[8];
    const float* bv = (const float*)d_in[9];
    const float* Wo = (const float*)d_in[10];
    const float* bo = (const float*)d_in[11];
    float* out = (float*)d_out;

    float *gq, *gk, *gv, *gctx, *gain, *gwin;
    cudaGetSymbolAddress((void**)&gq,   g_q);
    cudaGetSymbolAddress((void**)&gk,   g_k);
    cudaGetSymbolAddress((void**)&gv,   g_v);
    cudaGetSymbolAddress((void**)&gctx, g_ctx);
    cudaGetSymbolAddress((void**)&gain, g_ain);
    cudaGetSymbolAddress((void**)&gwin, g_win);

    float* aq = gain;
    float* ak = gain + (size_t)MTOT * DMODEL;
    float* av = gain + 2 * (size_t)MTOT * DMODEL;
    float* wq = gwin;
    float* wk = gwin + (size_t)DMODEL * DMODEL;
    float* wv = gwin + 2 * (size_t)DMODEL * DMODEL;
    float* wo = gwin + 3 * (size_t)DMODEL * DMODEL;

    cudaFuncSetAttribute(gemm_mma,
                         cudaFuncAttributeMaxDynamicSharedMemorySize, GEMM_SMEM);
    cudaFuncSetAttribute(gemm_qkv,
                         cudaFuncAttributeMaxDynamicSharedMemorySize, GEMM_SMEM);
    cudaFuncSetAttribute(attn_mma,
                         cudaFuncAttributeMaxDynamicSharedMemorySize, ATT_SMEM);

    // ---- fused prepass: tf32-round all activations and weights ----
    const size_t NA = (size_t)MTOT * DMODEL;      // 2^23
    const size_t NW = (size_t)DMODEL * DMODEL;    // 2^20
    const int nblk = (int)((3 * NA + 4 * NW) / 1024);   // 28672
    round_all<<<nblk, 256>>>(query, key_, value, Wq, Wk, Wv, Wo);

    // ---- fused Q/K/V projections (one launch, 1536 CTAs) ----
    dim3 qkvgrid(DMODEL / 128, MTOT / 128, 3);    // (8, 64, 3)
    gemm_qkv<<<qkvgrid, dim3(256), GEMM_SMEM>>>(aq, ak, av, wq, wk, wv,
                                                bq, bk, bv, gq, gk, gv);

    // ---- attention ----
    dim3 agrid(SEQ / 128, H_HEADS, BATCH);        // (16, 16, 4)
    attn_mma<<<agrid, dim3(128), ATT_SMEM>>>(gq, gk, gv, mask, gctx);

    // ---- output projection ----
    dim3 ggrid(DMODEL / 128, MTOT / 128);         // (8, 64)
    gemm_mma<<<ggrid, dim3(256), GEMM_SMEM>>>(gctx, wo, bo, out, 1);
}

// round 10
// speedup vs baseline: 1.8151x; 1.3513x over previous
#include <cuda_runtime.h>
#include <cuda_fp16.h>
#include <cstdint>

// ---------------- problem constants ----------------
#define H_HEADS 16
#define DMODEL  1024
#define BATCH   4
#define SEQ     2048
#define MTOT    (BATCH * SEQ)          // 8192

// ---------------- scratch (static device globals; no allocs) ----------------
__device__ __half g_q[(size_t)BATCH * H_HEADS * SEQ * 64];  // fp16, pre-scaled 0.125*log2e
__device__ __half g_k[(size_t)BATCH * H_HEADS * SEQ * 64];  // fp16
__device__ __half g_v[(size_t)BATCH * H_HEADS * SEQ * 64];  // fp16
__device__ float  g_ctx[(size_t)BATCH * SEQ * DMODEL];      // tf32-rounded (B,S,H*dk)
__device__ float  g_ain[3][(size_t)MTOT * DMODEL];          // tf32 copies of q/k/v inputs
__device__ float  g_win[4][(size_t)DMODEL * DMODEL];        // tf32 copies of Wq/Wk/Wv/Wo

// ---------------- helpers ----------------
__device__ __forceinline__ uint32_t smem_u32(const void* p) {
    uint32_t a;
    asm("{ .reg .u64 t; cvta.to.shared.u64 t, %1; cvt.u32.u64 %0, t; }"
        : "=r"(a) : "l"(p));
    return a;
}

__device__ __forceinline__ uint32_t f2tf(float x) {
    uint32_t r;
    asm("cvt.rna.tf32.f32 %0, %1;" : "=r"(r) : "f"(x));
    return r;
}

__device__ __forceinline__ float ex2(float x) {
    float y;
    asm("ex2.approx.f32 %0, %1;" : "=f"(y) : "f"(x));
    return y;
}

// pack two f32 into f16x2: lo = first arg, hi = second
__device__ __forceinline__ uint32_t pkh2(float lo, float hi) {
    uint32_t d;
    asm("cvt.rn.f16x2.f32 %0, %1, %2;" : "=r"(d) : "f"(hi), "f"(lo));
    return d;
}

// tf32 m16n8k8 (GEMMs)
__device__ __forceinline__ void mma_tf32(float* c, const uint32_t* a, const uint32_t* b) {
    asm volatile(
        "mma.sync.aligned.m16n8k8.row.col.f32.tf32.tf32.f32 "
        "{%0,%1,%2,%3},{%4,%5,%6,%7},{%8,%9},{%0,%1,%2,%3};"
        : "+f"(c[0]), "+f"(c[1]), "+f"(c[2]), "+f"(c[3])
        : "r"(a[0]), "r"(a[1]), "r"(a[2]), "r"(a[3]), "r"(b[0]), "r"(b[1]));
}

// fp16 m16n8k16, fp32 accumulate (attention)
__device__ __forceinline__ void mma_f16(float* c, const uint32_t* a, uint32_t b0, uint32_t b1) {
    asm volatile(
        "mma.sync.aligned.m16n8k16.row.col.f32.f16.f16.f32 "
        "{%0,%1,%2,%3},{%4,%5,%6,%7},{%8,%9},{%0,%1,%2,%3};"
        : "+f"(c[0]), "+f"(c[1]), "+f"(c[2]), "+f"(c[3])
        : "r"(a[0]), "r"(a[1]), "r"(a[2]), "r"(a[3]), "r"(b0), "r"(b1));
}

#define LDSM4(r0, r1, r2, r3, addr) \
    asm volatile("ldmatrix.sync.aligned.m8n8.x4.shared.b16 {%0,%1,%2,%3}, [%4];" \
                 : "=r"(r0), "=r"(r1), "=r"(r2), "=r"(r3) : "r"(addr))
#define LDSM4T(r0, r1, r2, r3, addr) \
    asm volatile("ldmatrix.sync.aligned.m8n8.x4.trans.shared.b16 {%0,%1,%2,%3}, [%4];" \
                 : "=r"(r0), "=r"(r1), "=r"(r2), "=r"(r3) : "r"(addr))

#define CP_ASYNC16(dst, src) \
    asm volatile("cp.async.cg.shared.global [%0], [%1], 16;" :: "r"(dst), "l"(src) : "memory")
#define CP_ASYNC4(dst, src) \
    asm volatile("cp.async.ca.shared.global [%0], [%1], 4;" :: "r"(dst), "l"(src) : "memory")
#define CP_COMMIT() asm volatile("cp.async.commit_group;" ::: "memory")
#define CP_WAIT1()  asm volatile("cp.async.wait_group 1;" ::: "memory")
#define CP_WAIT0()  asm volatile("cp.async.wait_group 0;" ::: "memory")

// ============================================================================
// fused tf32 rounding prepass: 3 activations (2^23 ea) + 4 weights (2^20 ea)
// ============================================================================
__global__ __launch_bounds__(256)
void round_all(const float* __restrict__ q, const float* __restrict__ k,
               const float* __restrict__ v, const float* __restrict__ wq,
               const float* __restrict__ wk, const float* __restrict__ wv,
               const float* __restrict__ wo)
{
    const size_t NAe = (size_t)MTOT * DMODEL;     // 2^23
    const size_t NWe = (size_t)DMODEL * DMODEL;   // 2^20
    size_t g = (((size_t)blockIdx.x * 256) + threadIdx.x) << 2;
    const float* src;
    float* dst;
    if (g < 3 * NAe) {
        int seg = (int)(g >> 23);
        size_t off = g & (NAe - 1);
        src = (seg == 0 ? q : (seg == 1 ? k : v)) + off;
        dst = g_ain[seg] + off;
    } else {
        size_t gw = g - 3 * NAe;
        int seg = (int)(gw >> 20);
        size_t off = gw & (NWe - 1);
        src = (seg == 0 ? wq : (seg == 1 ? wk : (seg == 2 ? wv : wo))) + off;
        dst = g_win[seg] + off;
    }
    float4 x = *(const float4*)src;
    x.x = __uint_as_float(f2tf(x.x));
    x.y = __uint_as_float(f2tf(x.y));
    x.z = __uint_as_float(f2tf(x.z));
    x.w = __uint_as_float(f2tf(x.w));
    *(float4*)dst = x;
}

// ============================================================================
// tf32 mma.sync GEMM-NT body (R6 pipeline: double buffer, 2 syncs/iter)
//   mode 1: fp32 row-major out (final output)
//   mode 0: fp16 head-split out (K, V)
//   mode 2: fp16 head-split out, x QSCALE (Q)
// ============================================================================
#define GS 36
#define GEMM_SMEM (2 * 2 * 128 * GS * 4)        // 73728 B
#define QSCALE (0.125f * 1.4426950408889634f)   // 1/sqrt(dk) * log2(e)

__device__ __forceinline__ void gemm_load_stage(uint32_t sbase, uint32_t woffB,
                                                const float* __restrict__ Ag,
                                                const float* __restrict__ Wg,
                                                int s, int k0, int tid)
{
#pragma unroll
    for (int i = 0; i < 4; i++) {
        int idx = tid + 256 * i;
        int r   = idx >> 3;
        int c4  = (idx & 7) << 2;
        uint32_t d = (uint32_t)(((s * 128 + r) * GS + c4) * 4);
        CP_ASYNC16(sbase + d,         Ag + (size_t)r * DMODEL + k0 + c4);
        CP_ASYNC16(sbase + woffB + d, Wg + (size_t)r * DMODEL + k0 + c4);
    }
}

__device__ __forceinline__ void gemm_body(const float* __restrict__ A,
                                          const float* __restrict__ W,
                                          const float* __restrict__ bias,
                                          float* __restrict__ C,
                                          __half* __restrict__ Ch,
                                          int mode, int bx, int by)
{
    extern __shared__ float sm[];
    const float* As  = sm;
    const float* Ws_ = sm + 2 * 128 * GS;
    const uint32_t sbase = smem_u32(sm);
    const uint32_t woffB = (uint32_t)(2 * 128 * GS * 4);

    const int tid  = threadIdx.x;
    const int lane = tid & 31, wid = tid >> 5;
    const int wm = wid >> 2, wn = wid & 3;
    const int r0 = lane >> 2, c0 = lane & 3;

    const int rowBase = by * 128;
    const int colBase = bx * 128;
    const float* Ag = A + (size_t)rowBase * DMODEL;
    const float* Wg = W + (size_t)colBase * DMODEL;

    float acc[4][4][4];
#pragma unroll
    for (int mf = 0; mf < 4; mf++)
#pragma unroll
        for (int nf = 0; nf < 4; nf++)
#pragma unroll
            for (int r = 0; r < 4; r++) acc[mf][nf][r] = 0.f;

    gemm_load_stage(sbase, woffB, Ag, Wg, 0, 0, tid);  CP_COMMIT();
    gemm_load_stage(sbase, woffB, Ag, Wg, 1, 32, tid); CP_COMMIT();

    for (int kt = 0; kt < DMODEL / 32; kt++) {
        CP_WAIT1();
        __syncthreads();
        const float* as = As  + (kt & 1) * 128 * GS;
        const float* ws = Ws_ + (kt & 1) * 128 * GS;
#pragma unroll
        for (int ks = 0; ks < 4; ks++) {
            const int kc = ks * 8;
            uint32_t af[4][4], bf[4][2];
#pragma unroll
            for (int mf = 0; mf < 4; mf++) {
                const float* ap = as + (wm * 64 + mf * 16 + r0) * GS + kc + c0;
                af[mf][0] = __float_as_uint(ap[0]);
                af[mf][1] = __float_as_uint(ap[8 * GS]);
                af[mf][2] = __float_as_uint(ap[4]);
                af[mf][3] = __float_as_uint(ap[8 * GS + 4]);
            }
#pragma unroll
            for (int nf = 0; nf < 4; nf++) {
                const float* wp = ws + (wn * 32 + nf * 8 + r0) * GS + kc + c0;
                bf[nf][0] = __float_as_uint(wp[0]);
                bf[nf][1] = __float_as_uint(wp[4]);
            }
#pragma unroll
            for (int mf = 0; mf < 4; mf++)
#pragma unroll
                for (int nf = 0; nf < 4; nf++)
                    mma_tf32(acc[mf][nf], af[mf], bf[nf]);
        }
        __syncthreads();
        if (kt + 2 < DMODEL / 32)
            gemm_load_stage(sbase, woffB, Ag, Wg, kt & 1, (kt + 2) * 32, tid);
        CP_COMMIT();
    }

    const float os = (mode == 2) ? QSCALE : 1.0f;
#pragma unroll
    for (int mf = 0; mf < 4; mf++) {
        const int m0 = rowBase + wm * 64 + mf * 16 + r0;
        const int m1 = m0 + 8;
#pragma unroll
        for (int nf = 0; nf < 4; nf++) {
            const int n = colBase + wn * 32 + nf * 8 + 2 * c0;
            float2 v0, v1;
            v0.x = acc[mf][nf][0] + bias[n];
            v0.y = acc[mf][nf][1] + bias[n + 1];
            v1.x = acc[mf][nf][2] + bias[n];
            v1.y = acc[mf][nf][3] + bias[n + 1];
            if (mode == 1) {
                *(float2*)(C + (size_t)m0 * DMODEL + n) = v0;
                *(float2*)(C + (size_t)m1 * DMODEL + n) = v1;
            } else {
                __half2 h0 = __floats2half2_rn(v0.x * os, v0.y * os);
                __half2 h1 = __floats2half2_rn(v1.x * os, v1.y * os);
                const int hh = n >> 6, dd = n & 63;
                const int b0 = m0 >> 11, s0 = m0 & (SEQ - 1);
                const int b1 = m1 >> 11, s1 = m1 & (SEQ - 1);
                *(__half2*)(Ch + ((((size_t)b0 * H_HEADS + hh) * SEQ + s0) << 6) + dd) = h0;
                *(__half2*)(Ch + ((((size_t)b1 * H_HEADS + hh) * SEQ + s1) << 6) + dd) = h1;
            }
        }
    }
}

// output projection
__global__ __launch_bounds__(256)
void gemm_mma(const float* __restrict__ A, const float* __restrict__ W,
              const float* __restrict__ bias, float* __restrict__ C)
{
    gemm_body(A, W, bias, C, nullptr, 1, blockIdx.x, blockIdx.y);
}

// fused Q/K/V projections (fp16 head-split outputs)
__global__ __launch_bounds__(256)
void gemm_qkv(const float* __restrict__ aq, const float* __restrict__ ak,
              const float* __restrict__ av, const float* __restrict__ wq,
              const float* __restrict__ wk, const float* __restrict__ wv,
              const float* __restrict__ bq, const float* __restrict__ bk,
              const float* __restrict__ bv, __half* __restrict__ cq,
              __half* __restrict__ ck, __half* __restrict__ cv)
{
    const int z = blockIdx.z;
    const float* A    = (z == 0) ? aq : ((z == 1) ? ak : av);
    const float* W    = (z == 0) ? wq : ((z == 1) ? wk : wv);
    const float* bias = (z == 0) ? bq : ((z == 1) ? bk : bv);
    __half*      Ch   = (z == 0) ? cq : ((z == 1) ? ck : cv);
    gemm_body(A, W, bias, nullptr, Ch, (z == 0) ? 2 : 0, blockIdx.x, blockIdx.y);
}

// ============================================================================
// Flash attention, fp16 m16n8k16 (fp32 accumulate), exp2-domain softmax.
//   q-tile 128, 4 warps, warp owns 32 q rows (2 m-frags).
//   Q frags in regs (fp16 gmem); K via non-trans ldmatrix; V via trans
//   ldmatrix; P: S C-frag -> A-frag by direct f16x2 packing (no shuffles).
//   K/V/mask double-buffered cp.async.
// ============================================================================
#define KST 72
#define VST 72
// Ks[2][64][KST]h + Vs[2][64][VST]h + Ms[2][64]i
#define ATT_SMEM ((2 * 64 * KST + 2 * 64 * VST) * 2 + 2 * 64 * 4)   // 37376 B

__device__ __forceinline__ void attn_fill(uint32_t kb, uint32_t vb, uint32_t mb,
                                          const __half* __restrict__ Kg,
                                          const __half* __restrict__ Vg,
                                          const int* __restrict__ mg,
                                          int kt, int tid)
{
#pragma unroll
    for (int i = 0; i < 4; i++) {
        int idx = tid + 128 * i;          // 0..511
        int r = idx >> 3, ch = idx & 7;   // row, 16B chunk
        CP_ASYNC16(kb + (uint32_t)(r * KST * 2 + ch * 16),
                   Kg + ((size_t)kt * 64 + r) * 64 + ch * 8);
        CP_ASYNC16(vb + (uint32_t)(r * VST * 2 + ch * 16),
                   Vg + ((size_t)kt * 64 + r) * 64 + ch * 8);
    }
    if (tid < 64) CP_ASYNC4(mb + (uint32_t)(tid * 4), mg + kt * 64 + tid);
}

__global__ __launch_bounds__(128, 2)
void attn_mma(const __half* __restrict__ Q, const __half* __restrict__ Kg_,
              const __half* __restrict__ Vg_, const int* __restrict__ mask,
              float* __restrict__ ctx)
{
    extern __shared__ float smf[];
    int* Ms = (int*)((char*)smf + (2 * 64 * KST + 2 * 64 * VST) * 2);

    const uint32_t sb  = smem_u32(smf);
    const uint32_t KsB = sb;
    const uint32_t VsB = sb + 2 * 64 * KST * 2;
    const uint32_t MsB = sb + (2 * 64 * KST + 2 * 64 * VST) * 2;

    const int tid  = threadIdx.x;
    const int lane = tid & 31, wid = tid >> 5;
    const int r0 = lane >> 2, c0 = lane & 3;
    const int mrow = lane & 7, mquad = lane >> 3;   // ldmatrix lane roles
    const int qt = blockIdx.x, h = blockIdx.y, b = blockIdx.z;

    const size_t bh = (size_t)b * H_HEADS + h;
    const __half* Qg = Q   + (bh * SEQ + (size_t)qt * 128) * 64;
    const __half* Kg = Kg_ + bh * SEQ * 64;
    const __half* Vg = Vg_ + bh * SEQ * 64;
    const int*    mg = mask + (size_t)b * SEQ;

    // Q fragments (m16n8k16 A-frag), registers for the whole kernel
    uint32_t qa[2][4][4];
    {
        const __half* Qw = Qg + (size_t)(wid * 32) * 64;
#pragma unroll
        for (int mf = 0; mf < 2; mf++)
#pragma unroll
            for (int kb = 0; kb < 4; kb++) {
                const __half* p = Qw + (size_t)(mf * 16 + r0) * 64 + kb * 16 + 2 * c0;
                qa[mf][kb][0] = *(const uint32_t*)(p);
                qa[mf][kb][1] = *(const uint32_t*)(p + 8 * 64);
                qa[mf][kb][2] = *(const uint32_t*)(p + 8);
                qa[mf][kb][3] = *(const uint32_t*)(p + 8 * 64 + 8);
            }
    }

    float o[2][8][4];
#pragma unroll
    for (int mf = 0; mf < 2; mf++)
#pragma unroll
        for (int df = 0; df < 8; df++)
#pragma unroll
            for (int r = 0; r < 4; r++) o[mf][df][r] = 0.f;

    float mprev[2][2], lsum[2][2];
#pragma unroll
    for (int mf = 0; mf < 2; mf++) {
        mprev[mf][0] = -1e30f; mprev[mf][1] = -1e30f;
        lsum[mf][0] = 0.f;     lsum[mf][1] = 0.f;
    }

    attn_fill(KsB, VsB, MsB, Kg, Vg, mg, 0, tid);
    CP_COMMIT();

    const int nkt = SEQ / 64;
    for (int kt = 0; kt < nkt; kt++) {
        CP_WAIT0();
        __syncthreads();

        const int cur = kt & 1;
        if (kt + 1 < nkt) {
            const int nxt = (kt + 1) & 1;
            attn_fill(KsB + (uint32_t)(nxt * 64 * KST * 2),
                      VsB + (uint32_t)(nxt * 64 * VST * 2),
                      MsB + (uint32_t)(nxt * 256),
                      Kg, Vg, mg, kt + 1, tid);
        }
        CP_COMMIT();

        const uint32_t ksB = KsB + (uint32_t)(cur * 64 * KST * 2);
        const uint32_t vsB = VsB + (uint32_t)(cur * 64 * VST * 2);
        const int*     ms_ = Ms + cur * 64;

        // -------- S = Q . K^T (fp16 m16n8k16; K frags via ldmatrix) --------
        float s[2][8][4];
#pragma unroll
        for (int mf = 0; mf < 2; mf++)
#pragma unroll
            for (int nf = 0; nf < 8; nf++)
#pragma unroll
                for (int r = 0; r < 4; r++) s[mf][nf][r] = 0.f;

#pragma unroll
        for (int kb = 0; kb < 4; kb++) {
#pragma unroll
            for (int nfp = 0; nfp < 4; nfp++) {
                // matrices: m0=(nf,dlo) m1=(nf,dhi) m2=(nf+1,dlo) m3=(nf+1,dhi)
                uint32_t addr = ksB + (uint32_t)(
                    (((nfp * 2 + (mquad >> 1)) * 8 + mrow) * KST
                     + kb * 16 + (mquad & 1) * 8) * 2);
                uint32_t b0, b1, b2, b3;
                LDSM4(b0, b1, b2, b3, addr);
                mma_f16(s[0][2 * nfp],     qa[0][kb], b0, b1);
                mma_f16(s[0][2 * nfp + 1], qa[0][kb], b2, b3);
                mma_f16(s[1][2 * nfp],     qa[1][kb], b0, b1);
                mma_f16(s[1][2 * nfp + 1], qa[1][kb], b2, b3);
            }
        }

        // -------- mask --------
#pragma unroll
        for (int nf = 0; nf < 8; nf++) {
            const int nc = nf * 8 + 2 * c0;
            const bool k0m = ms_[nc] != 0, k1m = ms_[nc + 1] != 0;
#pragma unroll
            for (int mf = 0; mf < 2; mf++) {
                s[mf][nf][0] = k0m ? s[mf][nf][0] : -1e9f;
                s[mf][nf][1] = k1m ? s[mf][nf][1] : -1e9f;
                s[mf][nf][2] = k0m ? s[mf][nf][2] : -1e9f;
                s[mf][nf][3] = k1m ? s[mf][nf][3] : -1e9f;
            }
        }

        // -------- online softmax (exp2 domain) --------
#pragma unroll
        for (int mf = 0; mf < 2; mf++) {
            float rmax0 = -1e30f, rmax1 = -1e30f;
#pragma unroll
            for (int nf = 0; nf < 8; nf++) {
                rmax0 = fmaxf(rmax0, fmaxf(s[mf][nf][0], s[mf][nf][1]));
                rmax1 = fmaxf(rmax1, fmaxf(s[mf][nf][2], s[mf][nf][3]));
            }
            rmax0 = fmaxf(rmax0, __shfl_xor_sync(0xffffffffu, rmax0, 1));
            rmax0 = fmaxf(rmax0, __shfl_xor_sync(0xffffffffu, rmax0, 2));
            rmax1 = fmaxf(rmax1, __shfl_xor_sync(0xffffffffu, rmax1, 1));
            rmax1 = fmaxf(rmax1, __shfl_xor_sync(0xffffffffu, rmax1, 2));

            const float mn0 = fmaxf(mprev[mf][0], rmax0);
            const float mn1 = fmaxf(mprev[mf][1], rmax1);
            const float fac0 = ex2(mprev[mf][0] - mn0);
            const float fac1 = ex2(mprev[mf][1] - mn1);

            float rs0 = 0.f, rs1 = 0.f;
#pragma unroll
            for (int nf = 0; nf < 8; nf++) {
                s[mf][nf][0] = ex2(s[mf][nf][0] - mn0);
                s[mf][nf][1] = ex2(s[mf][nf][1] - mn0);
                s[mf][nf][2] = ex2(s[mf][nf][2] - mn1);
                s[mf][nf][3] = ex2(s[mf][nf][3] - mn1);
                rs0 += s[mf][nf][0] + s[mf][nf][1];
                rs1 += s[mf][nf][2] + s[mf][nf][3];
            }
            rs0 += __shfl_xor_sync(0xffffffffu, rs0, 1);
            rs0 += __shfl_xor_sync(0xffffffffu, rs0, 2);
            rs1 += __shfl_xor_sync(0xffffffffu, rs1, 1);
            rs1 += __shfl_xor_sync(0xffffffffu, rs1, 2);

            lsum[mf][0] = lsum[mf][0] * fac0 + rs0;
            lsum[mf][1] = lsum[mf][1] * fac1 + rs1;
            mprev[mf][0] = mn0; mprev[mf][1] = mn1;
#pragma unroll
            for (int df = 0; df < 8; df++) {
                o[mf][df][0] *= fac0; o[mf][df][1] *= fac0;
                o[mf][df][2] *= fac1; o[mf][df][3] *= fac1;
            }
        }

        // -------- P: S C-frags -> fp16 A-frags (direct pack, no shuffles) --
        uint32_t pa[2][4][4];
#pragma unroll
        for (int mf = 0; mf < 2; mf++)
#pragma unroll
            for (int kb = 0; kb < 4; kb++) {
                pa[mf][kb][0] = pkh2(s[mf][2 * kb][0],     s[mf][2 * kb][1]);
                pa[mf][kb][1] = pkh2(s[mf][2 * kb][2],     s[mf][2 * kb][3]);
                pa[mf][kb][2] = pkh2(s[mf][2 * kb + 1][0], s[mf][2 * kb + 1][1]);
                pa[mf][kb][3] = pkh2(s[mf][2 * kb + 1][2], s[mf][2 * kb + 1][3]);
            }

        // -------- O += P . V (V frags via ldmatrix.trans) --------
#pragma unroll
        for (int kb = 0; kb < 4; kb++) {
#pragma unroll
            for (int dfp = 0; dfp < 4; dfp++) {
                // matrices: m0=(klo,d) m1=(khi,d) m2=(klo,d+1) m3=(khi,d+1)
                uint32_t addr = vsB + (uint32_t)(
                    ((kb * 16 + (mquad & 1) * 8 + mrow) * VST
                     + (dfp * 2 + (mquad >> 1)) * 8) * 2);
                uint32_t b0, b1, b2, b3;
                LDSM4T(b0, b1, b2, b3, addr);
                mma_f16(o[0][2 * dfp],     pa[0][kb], b0, b1);
                mma_f16(o[0][2 * dfp + 1], pa[0][kb], b2, b3);
                mma_f16(o[1][2 * dfp],     pa[1][kb], b0, b1);
                mma_f16(o[1][2 * dfp + 1], pa[1][kb], b2, b3);
            }
        }
    }

    // -------- finalize: ctx (B,S,H,64), tf32-rounded for the Wo GEMM --------
#pragma unroll
    for (int mf = 0; mf < 2; mf++) {
        const float inv0 = (lsum[mf][0] > 0.f) ? (1.f / lsum[mf][0]) : 0.f;
        const float inv1 = (lsum[mf][1] > 0.f) ? (1.f / lsum[mf][1]) : 0.f;
        const int q0 = qt * 128 + wid * 32 + mf * 16 + r0;
#pragma unroll
        for (int df = 0; df < 8; df++) {
            const int d = df * 8 + 2 * c0;
            float2 v0, v1;
            v0.x = __uint_as_float(f2tf(o[mf][df][0] * inv0));
            v0.y = __uint_as_float(f2tf(o[mf][df][1] * inv0));
            v1.x = __uint_as_float(f2tf(o[mf][df][2] * inv1));
            v1.y = __uint_as_float(f2tf(o[mf][df][3] * inv1));
            *(float2*)(ctx + ((size_t)(b * SEQ + q0) * H_HEADS + h) * 64 + d) = v0;
            *(float2*)(ctx + ((size_t)(b * SEQ + q0 + 8) * H_HEADS + h) * 64 + d) = v1;
        }
    }
}

// ============================================================================
// launch
// ============================================================================
extern "C" void kernel_launch(void* const* d_in, const int* in_sizes, int n_in,
                              void* d_out, int out_size)
{
    const float* query = (const float*)d_in[0];
    const float* key_  = (const float*)d_in[1];
    const float* value = (const float*)d_in[2];
    const int*   mask  = (const int*)  d_in[3];
    const float* Wq = (const float*)d_in[4];
    const float* bq = (const float*)d_in[5];
    const float* Wk = (const float*)d_in[6];
    const float* bk = (const float*)d_in[7];
    const float* Wv = (const float*)d_in[8];
    const float* bv = (const float*)d_in[9];
    const float* Wo = (const float*)d_in[10];
    const float* bo = (const float*)d_in[11];
    float* out = (float*)d_out;

    __half *gq, *gk, *gv;
    float *gctx, *gain, *gwin;
    cudaGetSymbolAddress((void**)&gq,   g_q);
    cudaGetSymbolAddress((void**)&gk,   g_k);
    cudaGetSymbolAddress((void**)&gv,   g_v);
    cudaGetSymbolAddress((void**)&gctx, g_ctx);
    cudaGetSymbolAddress((void**)&gain, g_ain);
    cudaGetSymbolAddress((void**)&gwin, g_win);

    float* aq = gain;
    float* ak = gain + (size_t)MTOT * DMODEL;
    float* av = gain + 2 * (size_t)MTOT * DMODEL;
    float* wq = gwin;
    float* wk = gwin + (size_t)DMODEL * DMODEL;
    float* wv = gwin + 2 * (size_t)DMODEL * DMODEL;
    float* wo = gwin + 3 * (size_t)DMODEL * DMODEL;

    cudaFuncSetAttribute(gemm_mma,
                         cudaFuncAttributeMaxDynamicSharedMemorySize, GEMM_SMEM);
    cudaFuncSetAttribute(gemm_qkv,
                         cudaFuncAttributeMaxDynamicSharedMemorySize, GEMM_SMEM);
    cudaFuncSetAttribute(attn_mma,
                         cudaFuncAttributeMaxDynamicSharedMemorySize, ATT_SMEM);

    // ---- fused prepass ----
    const size_t NA = (size_t)MTOT * DMODEL;      // 2^23
    const size_t NW = (size_t)DMODEL * DMODEL;    // 2^20
    const int nblk = (int)((3 * NA + 4 * NW) / 1024);   // 28672
    round_all<<<nblk, 256>>>(query, key_, value, Wq, Wk, Wv, Wo);

    // ---- fused Q/K/V projections (fp16 outputs) ----
    dim3 qkvgrid(DMODEL / 128, MTOT / 128, 3);    // (8, 64, 3)
    gemm_qkv<<<qkvgrid, dim3(256), GEMM_SMEM>>>(aq, ak, av, wq, wk, wv,
                                                bq, bk, bv, gq, gk, gv);

    // ---- attention (fp16 m16n8k16) ----
    dim3 agrid(SEQ / 128, H_HEADS, BATCH);        // (16, 16, 4)
    attn_mma<<<agrid, dim3(128), ATT_SMEM>>>(gq, gk, gv, mask, gctx);

    // ---- output projection ----
    dim3 ggrid(DMODEL / 128, MTOT / 128);         // (8, 64)
    gemm_mma<<<ggrid, dim3(256), GEMM_SMEM>>>(gctx, wo, bo, out);
}

// round 11
// speedup vs baseline: 2.7060x; 1.4908x over previous
#include <cuda_runtime.h>
#include <cuda_fp16.h>
#include <cstdint>

// ---------------- problem constants ----------------
#define H_HEADS 16
#define DMODEL  1024
#define BATCH   4
#define SEQ     2048
#define MTOT    (BATCH * SEQ)          // 8192

// ---------------- scratch (static device globals; no allocs) ----------------
__device__ __half g_q[(size_t)BATCH * H_HEADS * SEQ * 64];  // fp16, pre-scaled 0.125*log2e
__device__ __half g_k[(size_t)BATCH * H_HEADS * SEQ * 64];  // fp16
__device__ __half g_v[(size_t)BATCH * H_HEADS * SEQ * 64];  // fp16
__device__ __half g_ctx[(size_t)BATCH * SEQ * DMODEL];      // fp16 (B,S,H*dk)
__device__ __half g_ain[3][(size_t)MTOT * DMODEL];          // fp16 copies of q/k/v inputs
__device__ __half g_win[4][(size_t)DMODEL * DMODEL];        // fp16 copies of Wq/Wk/Wv/Wo

// ---------------- helpers ----------------
__device__ __forceinline__ uint32_t smem_u32(const void* p) {
    uint32_t a;
    asm("{ .reg .u64 t; cvta.to.shared.u64 t, %1; cvt.u32.u64 %0, t; }"
        : "=r"(a) : "l"(p));
    return a;
}

__device__ __forceinline__ float ex2(float x) {
    float y;
    asm("ex2.approx.f32 %0, %1;" : "=f"(y) : "f"(x));
    return y;
}

// pack two f32 into f16x2: lo = first arg, hi = second
__device__ __forceinline__ uint32_t pkh2(float lo, float hi) {
    uint32_t d;
    asm("cvt.rn.f16x2.f32 %0, %1, %2;" : "=r"(d) : "f"(hi), "f"(lo));
    return d;
}

// fp16 m16n8k16, fp32 accumulate
__device__ __forceinline__ void mma_f16(float* c, const uint32_t* a, uint32_t b0, uint32_t b1) {
    asm volatile(
        "mma.sync.aligned.m16n8k16.row.col.f32.f16.f16.f32 "
        "{%0,%1,%2,%3},{%4,%5,%6,%7},{%8,%9},{%0,%1,%2,%3};"
        : "+f"(c[0]), "+f"(c[1]), "+f"(c[2]), "+f"(c[3])
        : "r"(a[0]), "r"(a[1]), "r"(a[2]), "r"(a[3]), "r"(b0), "r"(b1));
}

#define LDSM4(r0, r1, r2, r3, addr) \
    asm volatile("ldmatrix.sync.aligned.m8n8.x4.shared.b16 {%0,%1,%2,%3}, [%4];" \
                 : "=r"(r0), "=r"(r1), "=r"(r2), "=r"(r3) : "r"(addr))
#define LDSM4T(r0, r1, r2, r3, addr) \
    asm volatile("ldmatrix.sync.aligned.m8n8.x4.trans.shared.b16 {%0,%1,%2,%3}, [%4];" \
                 : "=r"(r0), "=r"(r1), "=r"(r2), "=r"(r3) : "r"(addr))

#define CP_ASYNC16(dst, src) \
    asm volatile("cp.async.cg.shared.global [%0], [%1], 16;" :: "r"(dst), "l"(src) : "memory")
#define CP_ASYNC4(dst, src) \
    asm volatile("cp.async.ca.shared.global [%0], [%1], 4;" :: "r"(dst), "l"(src) : "memory")
#define CP_COMMIT() asm volatile("cp.async.commit_group;" ::: "memory")
#define CP_WAIT1()  asm volatile("cp.async.wait_group 1;" ::: "memory")
#define CP_WAIT0()  asm volatile("cp.async.wait_group 0;" ::: "memory")

// ============================================================================
// fused fp16 conversion prepass: 3 activations (2^23 ea) + 4 weights (2^20 ea)
// ============================================================================
__global__ __launch_bounds__(256)
void round_all(const float* __restrict__ q, const float* __restrict__ k,
               const float* __restrict__ v, const float* __restrict__ wq,
               const float* __restrict__ wk, const float* __restrict__ wv,
               const float* __restrict__ wo)
{
    const size_t NAe = (size_t)MTOT * DMODEL;     // 2^23
    const size_t NWe = (size_t)DMODEL * DMODEL;   // 2^20
    size_t g = (((size_t)blockIdx.x * 256) + threadIdx.x) << 2;
    const float* src;
    __half* dst;
    if (g < 3 * NAe) {
        int seg = (int)(g >> 23);
        size_t off = g & (NAe - 1);
        src = (seg == 0 ? q : (seg == 1 ? k : v)) + off;
        dst = g_ain[seg] + off;
    } else {
        size_t gw = g - 3 * NAe;
        int seg = (int)(gw >> 20);
        size_t off = gw & (NWe - 1);
        src = (seg == 0 ? wq : (seg == 1 ? wk : (seg == 2 ? wv : wo))) + off;
        dst = g_win[seg] + off;
    }
    float4 x = *(const float4*)src;
    __half2 h0 = __floats2half2_rn(x.x, x.y);
    __half2 h1 = __floats2half2_rn(x.z, x.w);
    *(__half2*)(dst)     = h0;
    *(__half2*)(dst + 2) = h1;
}

// ============================================================================
// fp16 m16n8k16 GEMM-NT, BK=64, double buffer (R6 pipeline structure),
// ldmatrix fragment loads.
//   C[m,n] = sum_k A[m,k] * W[n,k] + bias[n]
//   mode 1: fp32 row-major out (final output)
//   mode 0: fp16 head-split out (K, V)
//   mode 2: fp16 head-split out, x QSCALE (Q)
// ============================================================================
#define HST 72                                   // halves per tile row (144 B)
#define TILE_B (128 * HST * 2)                   // 18432 B per tile
#define GEMM_SMEM (4 * TILE_B)                   // 73728 B
#define QSCALE (0.125f * 1.4426950408889634f)    // 1/sqrt(dk) * log2(e)

__device__ __forceinline__ void gemm_load_stage(uint32_t sbase,
                                                const __half* __restrict__ Ag,
                                                const __half* __restrict__ Wg,
                                                int s, int k0, int tid)
{
    const uint32_t ab = sbase + (uint32_t)(s * TILE_B);          // A stage
    const uint32_t wb = ab + (uint32_t)(2 * TILE_B);             // W stage
#pragma unroll
    for (int i = 0; i < 4; i++) {
        int idx = tid + 256 * i;          // 0..1023
        int r = idx >> 3, ch = idx & 7;   // row, 16B chunk (8 halves)
        uint32_t d = (uint32_t)(r * HST * 2 + ch * 16);
        CP_ASYNC16(ab + d, Ag + (size_t)r * DMODEL + k0 + ch * 8);
        CP_ASYNC16(wb + d, Wg + (size_t)r * DMODEL + k0 + ch * 8);
    }
}

__device__ __forceinline__ void gemm_body(const __half* __restrict__ A,
                                          const __half* __restrict__ W,
                                          const float* __restrict__ bias,
                                          float* __restrict__ C,
                                          __half* __restrict__ Ch,
                                          int mode, int bx, int by)
{
    extern __shared__ char smc[];
    const uint32_t sbase = smem_u32(smc);

    const int tid  = threadIdx.x;
    const int lane = tid & 31, wid = tid >> 5;
    const int wm = wid >> 2, wn = wid & 3;        // warp grid 2 x 4
    const int r0 = lane >> 2, c0 = lane & 3;
    const int mrow = lane & 7, mquad = lane >> 3; // ldmatrix roles

    const int rowBase = by * 128;
    const int colBase = bx * 128;
    const __half* Ag = A + (size_t)rowBase * DMODEL;
    const __half* Wg = W + (size_t)colBase * DMODEL;

    float acc[4][4][4];
#pragma unroll
    for (int mf = 0; mf < 4; mf++)
#pragma unroll
        for (int nf = 0; nf < 4; nf++)
#pragma unroll
            for (int r = 0; r < 4; r++) acc[mf][nf][r] = 0.f;

    gemm_load_stage(sbase, Ag, Wg, 0, 0, tid);  CP_COMMIT();
    gemm_load_stage(sbase, Ag, Wg, 1, 64, tid); CP_COMMIT();

    const int NKT = DMODEL / 64;                  // 16
    for (int kt = 0; kt < NKT; kt++) {
        CP_WAIT1();
        __syncthreads();
        const uint32_t aT = sbase + (uint32_t)((kt & 1) * TILE_B);
        const uint32_t wT = aT + (uint32_t)(2 * TILE_B);
#pragma unroll
        for (int ks = 0; ks < 4; ks++) {
            const int kc = ks * 16;
            uint32_t af[4][4], bf[4][2];
#pragma unroll
            for (int mf = 0; mf < 4; mf++) {
                uint32_t addr = aT + (uint32_t)(
                    ((wm * 64 + mf * 16 + mrow + (mquad & 1) * 8) * HST
                     + kc + (mquad >> 1) * 8) * 2);
                LDSM4(af[mf][0], af[mf][1], af[mf][2], af[mf][3], addr);
            }
#pragma unroll
            for (int nfp = 0; nfp < 2; nfp++) {
                uint32_t addr = wT + (uint32_t)(
                    ((wn * 32 + (nfp * 2 + (mquad >> 1)) * 8 + mrow) * HST
                     + kc + (mquad & 1) * 8) * 2);
                uint32_t b0, b1, b2, b3;
                LDSM4(b0, b1, b2, b3, addr);
                bf[2 * nfp][0] = b0;     bf[2 * nfp][1] = b1;
                bf[2 * nfp + 1][0] = b2; bf[2 * nfp + 1][1] = b3;
            }
#pragma unroll
            for (int mf = 0; mf < 4; mf++)
#pragma unroll
                for (int nf = 0; nf < 4; nf++)
                    mma_f16(acc[mf][nf], af[mf], bf[nf][0], bf[nf][1]);
        }
        __syncthreads();
        if (kt + 2 < NKT)
            gemm_load_stage(sbase, Ag, Wg, kt & 1, (kt + 2) * 64, tid);
        CP_COMMIT();
    }

    const float os = (mode == 2) ? QSCALE : 1.0f;
#pragma unroll
    for (int mf = 0; mf < 4; mf++) {
        const int m0 = rowBase + wm * 64 + mf * 16 + r0;
        const int m1 = m0 + 8;
#pragma unroll
        for (int nf = 0; nf < 4; nf++) {
            const int n = colBase + wn * 32 + nf * 8 + 2 * c0;
            float2 v0, v1;
            v0.x = acc[mf][nf][0] + bias[n];
            v0.y = acc[mf][nf][1] + bias[n + 1];
            v1.x = acc[mf][nf][2] + bias[n];
            v1.y = acc[mf][nf][3] + bias[n + 1];
            if (mode == 1) {
                *(float2*)(C + (size_t)m0 * DMODEL + n) = v0;
                *(float2*)(C + (size_t)m1 * DMODEL + n) = v1;
            } else {
                __half2 h0 = __floats2half2_rn(v0.x * os, v0.y * os);
                __half2 h1 = __floats2half2_rn(v1.x * os, v1.y * os);
                const int hh = n >> 6, dd = n & 63;
                const int b0 = m0 >> 11, s0 = m0 & (SEQ - 1);
                const int b1 = m1 >> 11, s1 = m1 & (SEQ - 1);
                *(__half2*)(Ch + ((((size_t)b0 * H_HEADS + hh) * SEQ + s0) << 6) + dd) = h0;
                *(__half2*)(Ch + ((((size_t)b1 * H_HEADS + hh) * SEQ + s1) << 6) + dd) = h1;
            }
        }
    }
}

// output projection
__global__ __launch_bounds__(256)
void gemm_mma(const __half* __restrict__ A, const __half* __restrict__ W,
              const float* __restrict__ bias, float* __restrict__ C)
{
    gemm_body(A, W, bias, C, nullptr, 1, blockIdx.x, blockIdx.y);
}

// fused Q/K/V projections (fp16 head-split outputs)
__global__ __launch_bounds__(256)
void gemm_qkv(const __half* __restrict__ aq, const __half* __restrict__ ak,
              const __half* __restrict__ av, const __half* __restrict__ wq,
              const __half* __restrict__ wk, const __half* __restrict__ wv,
              const float* __restrict__ bq, const float* __restrict__ bk,
              const float* __restrict__ bv, __half* __restrict__ cq,
              __half* __restrict__ ck, __half* __restrict__ cv)
{
    const int z = blockIdx.z;
    const __half* A    = (z == 0) ? aq : ((z == 1) ? ak : av);
    const __half* W    = (z == 0) ? wq : ((z == 1) ? wk : wv);
    const float*  bias = (z == 0) ? bq : ((z == 1) ? bk : bv);
    __half*       Ch   = (z == 0) ? cq : ((z == 1) ? ck : cv);
    gemm_body(A, W, bias, nullptr, Ch, (z == 0) ? 2 : 0, blockIdx.x, blockIdx.y);
}

// ============================================================================
// Flash attention, fp16 m16n8k16 (fp32 accumulate), exp2-domain softmax.
//   (unchanged from R10 except ctx is now fp16)
// ============================================================================
#define KST 72
#define VST 72
#define ATT_SMEM ((2 * 64 * KST + 2 * 64 * VST) * 2 + 2 * 64 * 4)   // 37376 B

__device__ __forceinline__ void attn_fill(uint32_t kb, uint32_t vb, uint32_t mb,
                                          const __half* __restrict__ Kg,
                                          const __half* __restrict__ Vg,
                                          const int* __restrict__ mg,
                                          int kt, int tid)
{
#pragma unroll
    for (int i = 0; i < 4; i++) {
        int idx = tid + 128 * i;
        int r = idx >> 3, ch = idx & 7;
        CP_ASYNC16(kb + (uint32_t)(r * KST * 2 + ch * 16),
                   Kg + ((size_t)kt * 64 + r) * 64 + ch * 8);
        CP_ASYNC16(vb + (uint32_t)(r * VST * 2 + ch * 16),
                   Vg + ((size_t)kt * 64 + r) * 64 + ch * 8);
    }
    if (tid < 64) CP_ASYNC4(mb + (uint32_t)(tid * 4), mg + kt * 64 + tid);
}

__global__ __launch_bounds__(128, 2)
void attn_mma(const __half* __restrict__ Q, const __half* __restrict__ Kg_,
              const __half* __restrict__ Vg_, const int* __restrict__ mask,
              __half* __restrict__ ctx)
{
    extern __shared__ float smf[];
    int* Ms = (int*)((char*)smf + (2 * 64 * KST + 2 * 64 * VST) * 2);

    const uint32_t sb  = smem_u32(smf);
    const uint32_t KsB = sb;
    const uint32_t VsB = sb + 2 * 64 * KST * 2;
    const uint32_t MsB = sb + (2 * 64 * KST + 2 * 64 * VST) * 2;

    const int tid  = threadIdx.x;
    const int lane = tid & 31, wid = tid >> 5;
    const int r0 = lane >> 2, c0 = lane & 3;
    const int mrow = lane & 7, mquad = lane >> 3;
    const int qt = blockIdx.x, h = blockIdx.y, b = blockIdx.z;

    const size_t bh = (size_t)b * H_HEADS + h;
    const __half* Qg = Q   + (bh * SEQ + (size_t)qt * 128) * 64;
    const __half* Kg = Kg_ + bh * SEQ * 64;
    const __half* Vg = Vg_ + bh * SEQ * 64;
    const int*    mg = mask + (size_t)b * SEQ;

    uint32_t qa[2][4][4];
    {
        const __half* Qw = Qg + (size_t)(wid * 32) * 64;
#pragma unroll
        for (int mf = 0; mf < 2; mf++)
#pragma unroll
            for (int kb = 0; kb < 4; kb++) {
                const __half* p = Qw + (size_t)(mf * 16 + r0) * 64 + kb * 16 + 2 * c0;
                qa[mf][kb][0] = *(const uint32_t*)(p);
                qa[mf][kb][1] = *(const uint32_t*)(p + 8 * 64);
                qa[mf][kb][2] = *(const uint32_t*)(p + 8);
                qa[mf][kb][3] = *(const uint32_t*)(p + 8 * 64 + 8);
            }
    }

    float o[2][8][4];
#pragma unroll
    for (int mf = 0; mf < 2; mf++)
#pragma unroll
        for (int df = 0; df < 8; df++)
#pragma unroll
            for (int r = 0; r < 4; r++) o[mf][df][r] = 0.f;

    float mprev[2][2], lsum[2][2];
#pragma unroll
    for (int mf = 0; mf < 2; mf++) {
        mprev[mf][0] = -1e30f; mprev[mf][1] = -1e30f;
        lsum[mf][0] = 0.f;     lsum[mf][1] = 0.f;
    }

    attn_fill(KsB, VsB, MsB, Kg, Vg, mg, 0, tid);
    CP_COMMIT();

    const int nkt = SEQ / 64;
    for (int kt = 0; kt < nkt; kt++) {
        CP_WAIT0();
        __syncthreads();

        const int cur = kt & 1;
        if (kt + 1 < nkt) {
            const int nxt = (kt + 1) & 1;
            attn_fill(KsB + (uint32_t)(nxt * 64 * KST * 2),
                      VsB + (uint32_t)(nxt * 64 * VST * 2),
                      MsB + (uint32_t)(nxt * 256),
                      Kg, Vg, mg, kt + 1, tid);
        }
        CP_COMMIT();

        const uint32_t ksB = KsB + (uint32_t)(cur * 64 * KST * 2);
        const uint32_t vsB = VsB + (uint32_t)(cur * 64 * VST * 2);
        const int*     ms_ = Ms + cur * 64;

        float s[2][8][4];
#pragma unroll
        for (int mf = 0; mf < 2; mf++)
#pragma unroll
            for (int nf = 0; nf < 8; nf++)
#pragma unroll
                for (int r = 0; r < 4; r++) s[mf][nf][r] = 0.f;

#pragma unroll
        for (int kb = 0; kb < 4; kb++) {
#pragma unroll
            for (int nfp = 0; nfp < 4; nfp++) {
                uint32_t addr = ksB + (uint32_t)(
                    (((nfp * 2 + (mquad >> 1)) * 8 + mrow) * KST
                     + kb * 16 + (mquad & 1) * 8) * 2);
                uint32_t b0, b1, b2, b3;
                LDSM4(b0, b1, b2, b3, addr);
                mma_f16(s[0][2 * nfp],     qa[0][kb], b0, b1);
                mma_f16(s[0][2 * nfp + 1], qa[0][kb], b2, b3);
                mma_f16(s[1][2 * nfp],     qa[1][kb], b0, b1);
                mma_f16(s[1][2 * nfp + 1], qa[1][kb], b2, b3);
            }
        }

#pragma unroll
        for (int nf = 0; nf < 8; nf++) {
            const int nc = nf * 8 + 2 * c0;
            const bool k0m = ms_[nc] != 0, k1m = ms_[nc + 1] != 0;
#pragma unroll
            for (int mf = 0; mf < 2; mf++) {
                s[mf][nf][0] = k0m ? s[mf][nf][0] : -1e9f;
                s[mf][nf][1] = k1m ? s[mf][nf][1] : -1e9f;
                s[mf][nf][2] = k0m ? s[mf][nf][2] : -1e9f;
                s[mf][nf][3] = k1m ? s[mf][nf][3] : -1e9f;
            }
        }

#pragma unroll
        for (int mf = 0; mf < 2; mf++) {
            float rmax0 = -1e30f, rmax1 = -1e30f;
#pragma unroll
            for (int nf = 0; nf < 8; nf++) {
                rmax0 = fmaxf(rmax0, fmaxf(s[mf][nf][0], s[mf][nf][1]));
                rmax1 = fmaxf(rmax1, fmaxf(s[mf][nf][2], s[mf][nf][3]));
            }
            rmax0 = fmaxf(rmax0, __shfl_xor_sync(0xffffffffu, rmax0, 1));
            rmax0 = fmaxf(rmax0, __shfl_xor_sync(0xffffffffu, rmax0, 2));
            rmax1 = fmaxf(rmax1, __shfl_xor_sync(0xffffffffu, rmax1, 1));
            rmax1 = fmaxf(rmax1, __shfl_xor_sync(0xffffffffu, rmax1, 2));

            const float mn0 = fmaxf(mprev[mf][0], rmax0);
            const float mn1 = fmaxf(mprev[mf][1], rmax1);
            const float fac0 = ex2(mprev[mf][0] - mn0);
            const float fac1 = ex2(mprev[mf][1] - mn1);

            float rs0 = 0.f, rs1 = 0.f;
#pragma unroll
            for (int nf = 0; nf < 8; nf++) {
                s[mf][nf][0] = ex2(s[mf][nf][0] - mn0);
                s[mf][nf][1] = ex2(s[mf][nf][1] - mn0);
                s[mf][nf][2] = ex2(s[mf][nf][2] - mn1);
                s[mf][nf][3] = ex2(s[mf][nf][3] - mn1);
                rs0 += s[mf][nf][0] + s[mf][nf][1];
                rs1 += s[mf][nf][2] + s[mf][nf][3];
            }
            rs0 += __shfl_xor_sync(0xffffffffu, rs0, 1);
            rs0 += __shfl_xor_sync(0xffffffffu, rs0, 2);
            rs1 += __shfl_xor_sync(0xffffffffu, rs1, 1);
            rs1 += __shfl_xor_sync(0xffffffffu, rs1, 2);

            lsum[mf][0] = lsum[mf][0] * fac0 + rs0;
            lsum[mf][1] = lsum[mf][1] * fac1 + rs1;
            mprev[mf][0] = mn0; mprev[mf][1] = mn1;
#pragma unroll
            for (int df = 0; df < 8; df++) {
                o[mf][df][0] *= fac0; o[mf][df][1] *= fac0;
                o[mf][df][2] *= fac1; o[mf][df][3] *= fac1;
            }
        }

        uint32_t pa[2][4][4];
#pragma unroll
        for (int mf = 0; mf < 2; mf++)
#pragma unroll
            for (int kb = 0; kb < 4; kb++) {
                pa[mf][kb][0] = pkh2(s[mf][2 * kb][0],     s[mf][2 * kb][1]);
                pa[mf][kb][1] = pkh2(s[mf][2 * kb][2],     s[mf][2 * kb][3]);
                pa[mf][kb][2] = pkh2(s[mf][2 * kb + 1][0], s[mf][2 * kb + 1][1]);
                pa[mf][kb][3] = pkh2(s[mf][2 * kb + 1][2], s[mf][2 * kb + 1][3]);
            }

#pragma unroll
        for (int kb = 0; kb < 4; kb++) {
#pragma unroll
            for (int dfp = 0; dfp < 4; dfp++) {
                uint32_t addr = vsB + (uint32_t)(
                    ((kb * 16 + (mquad & 1) * 8 + mrow) * VST
                     + (dfp * 2 + (mquad >> 1)) * 8) * 2);
                uint32_t b0, b1, b2, b3;
                LDSM4T(b0, b1, b2, b3, addr);
                mma_f16(o[0][2 * dfp],     pa[0][kb], b0, b1);
                mma_f16(o[0][2 * dfp + 1], pa[0][kb], b2, b3);
                mma_f16(o[1][2 * dfp],     pa[1][kb], b0, b1);
                mma_f16(o[1][2 * dfp + 1], pa[1][kb], b2, b3);
            }
        }
    }

    // -------- finalize: ctx (B,S,H,64) as fp16 for the Wo GEMM --------
#pragma unroll
    for (int mf = 0; mf < 2; mf++) {
        const float inv0 = (lsum[mf][0] > 0.f) ? (1.f / lsum[mf][0]) : 0.f;
        const float inv1 = (lsum[mf][1] > 0.f) ? (1.f / lsum[mf][1]) : 0.f;
        const int q0 = qt * 128 + wid * 32 + mf * 16 + r0;
#pragma unroll
        for (int df = 0; df < 8; df++) {
            const int d = df * 8 + 2 * c0;
            __half2 h0 = __floats2half2_rn(o[mf][df][0] * inv0, o[mf][df][1] * inv0);
            __half2 h1 = __floats2half2_rn(o[mf][df][2] * inv1, o[mf][df][3] * inv1);
            *(__half2*)(ctx + ((size_t)(b * SEQ + q0) * H_HEADS + h) * 64 + d) = h0;
            *(__half2*)(ctx + ((size_t)(b * SEQ + q0 + 8) * H_HEADS + h) * 64 + d) = h1;
        }
    }
}

// ============================================================================
// launch
// ============================================================================
extern "C" void kernel_launch(void* const* d_in, const int* in_sizes, int n_in,
                              void* d_out, int out_size)
{
    const float* query = (const float*)d_in[0];
    const float* key_  = (const float*)d_in[1];
    const float* value = (const float*)d_in[2];
    const int*   mask  = (const int*)  d_in[3];
    const float* Wq = (const float*)d_in[4];
    const float* bq = (const float*)d_in[5];
    const float* Wk = (const float*)d_in[6];
    const float* bk = (const float*)d_in[7];
    const float* Wv = (const float*)d_in[8];
    const float* bv = (const float*)d_in[9];
    const float* Wo = (const float*)d_in[10];
    const float* bo = (const float*)d_in[11];
    float* out = (float*)d_out;

    __half *gq, *gk, *gv, *gctx, *gain, *gwin;
    cudaGetSymbolAddress((void**)&gq,   g_q);
    cudaGetSymbolAddress((void**)&gk,   g_k);
    cudaGetSymbolAddress((void**)&gv,   g_v);
    cudaGetSymbolAddress((void**)&gctx, g_ctx);
    cudaGetSymbolAddress((void**)&gain, g_ain);
    cudaGetSymbolAddress((void**)&gwin, g_win);

    __half* aq = gain;
    __half* ak = gain + (size_t)MTOT * DMODEL;
    __half* av = gain + 2 * (size_t)MTOT * DMODEL;
    __half* wq = gwin;
    __half* wk = gwin + (size_t)DMODEL * DMODEL;
    __half* wv = gwin + 2 * (size_t)DMODEL * DMODEL;
    __half* wo = gwin + 3 * (size_t)DMODEL * DMODEL;

    cudaFuncSetAttribute(gemm_mma,
                         cudaFuncAttributeMaxDynamicSharedMemorySize, GEMM_SMEM);
    cudaFuncSetAttribute(gemm_qkv,
                         cudaFuncAttributeMaxDynamicSharedMemorySize, GEMM_SMEM);
    cudaFuncSetAttribute(attn_mma,
                         cudaFuncAttributeMaxDynamicSharedMemorySize, ATT_SMEM);

    // ---- fused fp16 conversion prepass ----
    const size_t NA = (size_t)MTOT * DMODEL;      // 2^23
    const size_t NW = (size_t)DMODEL * DMODEL;    // 2^20
    const int nblk = (int)((3 * NA + 4 * NW) / 1024);   // 28672
    round_all<<<nblk, 256>>>(query, key_, value, Wq, Wk, Wv, Wo);

    // ---- fused Q/K/V projections (fp16 in, fp16 out) ----
    dim3 qkvgrid(DMODEL / 128, MTOT / 128, 3);    // (8, 64, 3)
    gemm_qkv<<<qkvgrid, dim3(256), GEMM_SMEM>>>(aq, ak, av, wq, wk, wv,
                                                bq, bk, bv, gq, gk, gv);

    // ---- attention (fp16 m16n8k16) ----
    dim3 agrid(SEQ / 128, H_HEADS, BATCH);        // (16, 16, 4)
    attn_mma<<<agrid, dim3(128), ATT_SMEM>>>(gq, gk, gv, mask, gctx);

    // ---- output projection (fp16 in, fp32 out) ----
    dim3 ggrid(DMODEL / 128, MTOT / 128);         // (8, 64)
    gemm_mma<<<ggrid, dim3(256), GEMM_SMEM>>>(gctx, wo, bo, out);
}

// round 12
// speedup vs baseline: 2.7644x; 1.0216x over previous
#include <cuda_runtime.h>
#include <cuda_fp16.h>
#include <cstdint>

// ---------------- problem constants ----------------
#define H_HEADS 16
#define DMODEL  1024
#define BATCH   4
#define SEQ     2048
#define MTOT    (BATCH * SEQ)          // 8192

// ---------------- scratch (static device globals; no allocs) ----------------
__device__ __half g_q[(size_t)BATCH * H_HEADS * SEQ * 64];  // fp16, pre-scaled 0.125*log2e
__device__ __half g_k[(size_t)BATCH * H_HEADS * SEQ * 64];  // fp16
__device__ __half g_v[(size_t)BATCH * H_HEADS * SEQ * 64];  // fp16
__device__ __half g_ctx[(size_t)BATCH * SEQ * DMODEL];      // fp16 (B,S,H*dk)
__device__ __half g_ain[3][(size_t)MTOT * DMODEL];          // fp16 copies of q/k/v inputs
__device__ __half g_win[4][(size_t)DMODEL * DMODEL];        // fp16 copies of Wq/Wk/Wv/Wo

// ---------------- helpers ----------------
__device__ __forceinline__ uint32_t smem_u32(const void* p) {
    uint32_t a;
    asm("{ .reg .u64 t; cvta.to.shared.u64 t, %1; cvt.u32.u64 %0, t; }"
        : "=r"(a) : "l"(p));
    return a;
}

__device__ __forceinline__ float ex2(float x) {
    float y;
    asm("ex2.approx.f32 %0, %1;" : "=f"(y) : "f"(x));
    return y;
}

// pack two f32 into f16x2: lo = first arg, hi = second
__device__ __forceinline__ uint32_t pkh2(float lo, float hi) {
    uint32_t d;
    asm("cvt.rn.f16x2.f32 %0, %1, %2;" : "=r"(d) : "f"(hi), "f"(lo));
    return d;
}

// fp16 m16n8k16, fp32 accumulate
__device__ __forceinline__ void mma_f16(float* c, const uint32_t* a, uint32_t b0, uint32_t b1) {
    asm volatile(
        "mma.sync.aligned.m16n8k16.row.col.f32.f16.f16.f32 "
        "{%0,%1,%2,%3},{%4,%5,%6,%7},{%8,%9},{%0,%1,%2,%3};"
        : "+f"(c[0]), "+f"(c[1]), "+f"(c[2]), "+f"(c[3])
        : "r"(a[0]), "r"(a[1]), "r"(a[2]), "r"(a[3]), "r"(b0), "r"(b1));
}

#define LDSM4(r0, r1, r2, r3, addr) \
    asm volatile("ldmatrix.sync.aligned.m8n8.x4.shared.b16 {%0,%1,%2,%3}, [%4];" \
                 : "=r"(r0), "=r"(r1), "=r"(r2), "=r"(r3) : "r"(addr))
#define LDSM4T(r0, r1, r2, r3, addr) \
    asm volatile("ldmatrix.sync.aligned.m8n8.x4.trans.shared.b16 {%0,%1,%2,%3}, [%4];" \
                 : "=r"(r0), "=r"(r1), "=r"(r2), "=r"(r3) : "r"(addr))

#define CP_ASYNC16(dst, src) \
    asm volatile("cp.async.cg.shared.global [%0], [%1], 16;" :: "r"(dst), "l"(src) : "memory")
#define CP_ASYNC4(dst, src) \
    asm volatile("cp.async.ca.shared.global [%0], [%1], 4;" :: "r"(dst), "l"(src) : "memory")
#define CP_COMMIT() asm volatile("cp.async.commit_group;" ::: "memory")
#define CP_WAIT1()  asm volatile("cp.async.wait_group 1;" ::: "memory")
#define CP_WAIT0()  asm volatile("cp.async.wait_group 0;" ::: "memory")

// ============================================================================
// fused fp16 conversion prepass, 4 float4s per thread (MLP=4)
// ============================================================================
#define PRE_BLKS 7168
__global__ __launch_bounds__(256)
void round_all(const float* __restrict__ q, const float* __restrict__ k,
               const float* __restrict__ v, const float* __restrict__ wq,
               const float* __restrict__ wk, const float* __restrict__ wv,
               const float* __restrict__ wo)
{
    const size_t NAe = (size_t)MTOT * DMODEL;     // 2^23
    const size_t NWe = (size_t)DMODEL * DMODEL;   // 2^20
    const size_t stride = (size_t)PRE_BLKS * 256;
    size_t base = (size_t)blockIdx.x * 256 + threadIdx.x;
#pragma unroll
    for (int it = 0; it < 4; it++) {
        size_t g = (base + it * stride) << 2;     // float index
        const float* src;
        __half* dst;
        if (g < 3 * NAe) {
            int seg = (int)(g >> 23);
            size_t off = g & (NAe - 1);
            src = (seg == 0 ? q : (seg == 1 ? k : v)) + off;
            dst = g_ain[seg] + off;
        } else {
            size_t gw = g - 3 * NAe;
            int seg = (int)(gw >> 20);
            size_t off = gw & (NWe - 1);
            src = (seg == 0 ? wq : (seg == 1 ? wk : (seg == 2 ? wv : wo))) + off;
            dst = g_win[seg] + off;
        }
        float4 x = *(const float4*)src;
        __half2 h0 = __floats2half2_rn(x.x, x.y);
        __half2 h1 = __floats2half2_rn(x.z, x.w);
        *(__half2*)(dst)     = h0;
        *(__half2*)(dst + 2) = h1;
    }
}

// ============================================================================
// fp16 m16n8k16 GEMM-NT, BK=64, double buffer, 128 threads (4 warps, 2x2),
// warp tile 64x64 (4 mf x 8 nf) — 32 MMA per 8 LDSM4 per kstep.
//   C[m,n] = sum_k A[m,k] * W[n,k] + bias[n]
//   mode 1: fp32 row-major out (final output)
//   mode 0: fp16 head-split out (K, V)
//   mode 2: fp16 head-split out, x QSCALE (Q)
// ============================================================================
#define HST 72                                   // halves per tile row (144 B)
#define TILE_B (128 * HST * 2)                   // 18432 B per tile
#define GEMM_SMEM (4 * TILE_B)                   // 73728 B
#define QSCALE (0.125f * 1.4426950408889634f)    // 1/sqrt(dk) * log2(e)

__device__ __forceinline__ void gemm_load_stage(uint32_t sbase,
                                                const __half* __restrict__ Ag,
                                                const __half* __restrict__ Wg,
                                                int s, int k0, int tid)
{
    const uint32_t ab = sbase + (uint32_t)(s * TILE_B);
    const uint32_t wb = ab + (uint32_t)(2 * TILE_B);
#pragma unroll
    for (int i = 0; i < 8; i++) {
        int idx = tid + 128 * i;          // 0..1023
        int r = idx >> 3, ch = idx & 7;
        uint32_t d = (uint32_t)(r * HST * 2 + ch * 16);
        CP_ASYNC16(ab + d, Ag + (size_t)r * DMODEL + k0 + ch * 8);
        CP_ASYNC16(wb + d, Wg + (size_t)r * DMODEL + k0 + ch * 8);
    }
}

__device__ __forceinline__ void gemm_body(const __half* __restrict__ A,
                                          const __half* __restrict__ W,
                                          const float* __restrict__ bias,
                                          float* __restrict__ C,
                                          __half* __restrict__ Ch,
                                          int mode, int bx, int by)
{
    extern __shared__ char smc[];
    const uint32_t sbase = smem_u32(smc);

    const int tid  = threadIdx.x;
    const int lane = tid & 31, wid = tid >> 5;
    const int wm = wid >> 1, wn = wid & 1;        // warp grid 2 x 2
    const int r0 = lane >> 2, c0 = lane & 3;
    const int mrow = lane & 7, mquad = lane >> 3;

    const int rowBase = by * 128;
    const int colBase = bx * 128;
    const __half* Ag = A + (size_t)rowBase * DMODEL;
    const __half* Wg = W + (size_t)colBase * DMODEL;

    float acc[4][8][4];
#pragma unroll
    for (int mf = 0; mf < 4; mf++)
#pragma unroll
        for (int nf = 0; nf < 8; nf++)
#pragma unroll
            for (int r = 0; r < 4; r++) acc[mf][nf][r] = 0.f;

    gemm_load_stage(sbase, Ag, Wg, 0, 0, tid);  CP_COMMIT();
    gemm_load_stage(sbase, Ag, Wg, 1, 64, tid); CP_COMMIT();

    const int NKT = DMODEL / 64;                  // 16
    for (int kt = 0; kt < NKT; kt++) {
        CP_WAIT1();
        __syncthreads();
        const uint32_t aT = sbase + (uint32_t)((kt & 1) * TILE_B);
        const uint32_t wT = aT + (uint32_t)(2 * TILE_B);
#pragma unroll
        for (int ks = 0; ks < 4; ks++) {
            const int kc = ks * 16;
            uint32_t af[4][4], bf[8][2];
#pragma unroll
            for (int mf = 0; mf < 4; mf++) {
                uint32_t addr = aT + (uint32_t)(
                    ((wm * 64 + mf * 16 + mrow + (mquad & 1) * 8) * HST
                     + kc + (mquad >> 1) * 8) * 2);
                LDSM4(af[mf][0], af[mf][1], af[mf][2], af[mf][3], addr);
            }
#pragma unroll
            for (int nfp = 0; nfp < 4; nfp++) {
                uint32_t addr = wT + (uint32_t)(
                    ((wn * 64 + (nfp * 2 + (mquad >> 1)) * 8 + mrow) * HST
                     + kc + (mquad & 1) * 8) * 2);
                uint32_t b0, b1, b2, b3;
                LDSM4(b0, b1, b2, b3, addr);
                bf[2 * nfp][0] = b0;     bf[2 * nfp][1] = b1;
                bf[2 * nfp + 1][0] = b2; bf[2 * nfp + 1][1] = b3;
            }
#pragma unroll
            for (int mf = 0; mf < 4; mf++)
#pragma unroll
                for (int nf = 0; nf < 8; nf++)
                    mma_f16(acc[mf][nf], af[mf], bf[nf][0], bf[nf][1]);
        }
        __syncthreads();
        if (kt + 2 < NKT)
            gemm_load_stage(sbase, Ag, Wg, kt & 1, (kt + 2) * 64, tid);
        CP_COMMIT();
    }

    const float os = (mode == 2) ? QSCALE : 1.0f;
#pragma unroll
    for (int mf = 0; mf < 4; mf++) {
        const int m0 = rowBase + wm * 64 + mf * 16 + r0;
        const int m1 = m0 + 8;
#pragma unroll
        for (int nf = 0; nf < 8; nf++) {
            const int n = colBase + wn * 64 + nf * 8 + 2 * c0;
            float2 v0, v1;
            v0.x = acc[mf][nf][0] + bias[n];
            v0.y = acc[mf][nf][1] + bias[n + 1];
            v1.x = acc[mf][nf][2] + bias[n];
            v1.y = acc[mf][nf][3] + bias[n + 1];
            if (mode == 1) {
                *(float2*)(C + (size_t)m0 * DMODEL + n) = v0;
                *(float2*)(C + (size_t)m1 * DMODEL + n) = v1;
            } else {
                __half2 h0 = __floats2half2_rn(v0.x * os, v0.y * os);
                __half2 h1 = __floats2half2_rn(v1.x * os, v1.y * os);
                const int hh = n >> 6, dd = n & 63;
                const int b0 = m0 >> 11, s0 = m0 & (SEQ - 1);
                const int b1 = m1 >> 11, s1 = m1 & (SEQ - 1);
                *(__half2*)(Ch + ((((size_t)b0 * H_HEADS + hh) * SEQ + s0) << 6) + dd) = h0;
                *(__half2*)(Ch + ((((size_t)b1 * H_HEADS + hh) * SEQ + s1) << 6) + dd) = h1;
            }
        }
    }
}

// output projection
__global__ __launch_bounds__(128, 2)
void gemm_mma(const __half* __restrict__ A, const __half* __restrict__ W,
              const float* __restrict__ bias, float* __restrict__ C)
{
    gemm_body(A, W, bias, C, nullptr, 1, blockIdx.x, blockIdx.y);
}

// fused Q/K/V projections (fp16 head-split outputs)
__global__ __launch_bounds__(128, 2)
void gemm_qkv(const __half* __restrict__ aq, const __half* __restrict__ ak,
              const __half* __restrict__ av, const __half* __restrict__ wq,
              const __half* __restrict__ wk, const __half* __restrict__ wv,
              const float* __restrict__ bq, const float* __restrict__ bk,
              const float* __restrict__ bv, __half* __restrict__ cq,
              __half* __restrict__ ck, __half* __restrict__ cv)
{
    const int z = blockIdx.z;
    const __half* A    = (z == 0) ? aq : ((z == 1) ? ak : av);
    const __half* W    = (z == 0) ? wq : ((z == 1) ? wk : wv);
    const float*  bias = (z == 0) ? bq : ((z == 1) ? bk : bv);
    __half*       Ch   = (z == 0) ? cq : ((z == 1) ? ck : cv);
    gemm_body(A, W, bias, nullptr, Ch, (z == 0) ? 2 : 0, blockIdx.x, blockIdx.y);
}

// ============================================================================
// Flash attention, fp16 m16n8k16 (fp32 accumulate), exp2-domain softmax.
//   (unchanged from R11 — known good)
// ============================================================================
#define KST 72
#define VST 72
#define ATT_SMEM ((2 * 64 * KST + 2 * 64 * VST) * 2 + 2 * 64 * 4)   // 37376 B

__device__ __forceinline__ void attn_fill(uint32_t kb, uint32_t vb, uint32_t mb,
                                          const __half* __restrict__ Kg,
                                          const __half* __restrict__ Vg,
                                          const int* __restrict__ mg,
                                          int kt, int tid)
{
#pragma unroll
    for (int i = 0; i < 4; i++) {
        int idx = tid + 128 * i;
        int r = idx >> 3, ch = idx & 7;
        CP_ASYNC16(kb + (uint32_t)(r * KST * 2 + ch * 16),
                   Kg + ((size_t)kt * 64 + r) * 64 + ch * 8);
        CP_ASYNC16(vb + (uint32_t)(r * VST * 2 + ch * 16),
                   Vg + ((size_t)kt * 64 + r) * 64 + ch * 8);
    }
    if (tid < 64) CP_ASYNC4(mb + (uint32_t)(tid * 4), mg + kt * 64 + tid);
}

__global__ __launch_bounds__(128, 2)
void attn_mma(const __half* __restrict__ Q, const __half* __restrict__ Kg_,
              const __half* __restrict__ Vg_, const int* __restrict__ mask,
              __half* __restrict__ ctx)
{
    extern __shared__ float smf[];
    int* Ms = (int*)((char*)smf + (2 * 64 * KST + 2 * 64 * VST) * 2);

    const uint32_t sb  = smem_u32(smf);
    const uint32_t KsB = sb;
    const uint32_t VsB = sb + 2 * 64 * KST * 2;
    const uint32_t MsB = sb + (2 * 64 * KST + 2 * 64 * VST) * 2;

    const int tid  = threadIdx.x;
    const int lane = tid & 31, wid = tid >> 5;
    const int r0 = lane >> 2, c0 = lane & 3;
    const int mrow = lane & 7, mquad = lane >> 3;
    const int qt = blockIdx.x, h = blockIdx.y, b = blockIdx.z;

    const size_t bh = (size_t)b * H_HEADS + h;
    const __half* Qg = Q   + (bh * SEQ + (size_t)qt * 128) * 64;
    const __half* Kg = Kg_ + bh * SEQ * 64;
    const __half* Vg = Vg_ + bh * SEQ * 64;
    const int*    mg = mask + (size_t)b * SEQ;

    uint32_t qa[2][4][4];
    {
        const __half* Qw = Qg + (size_t)(wid * 32) * 64;
#pragma unroll
        for (int mf = 0; mf < 2; mf++)
#pragma unroll
            for (int kb = 0; kb < 4; kb++) {
                const __half* p = Qw + (size_t)(mf * 16 + r0) * 64 + kb * 16 + 2 * c0;
                qa[mf][kb][0] = *(const uint32_t*)(p);
                qa[mf][kb][1] = *(const uint32_t*)(p + 8 * 64);
                qa[mf][kb][2] = *(const uint32_t*)(p + 8);
                qa[mf][kb][3] = *(const uint32_t*)(p + 8 * 64 + 8);
            }
    }

    float o[2][8][4];
#pragma unroll
    for (int mf = 0; mf < 2; mf++)
#pragma unroll
        for (int df = 0; df < 8; df++)
#pragma unroll
            for (int r = 0; r < 4; r++) o[mf][df][r] = 0.f;

    float mprev[2][2], lsum[2][2];
#pragma unroll
    for (int mf = 0; mf < 2; mf++) {
        mprev[mf][0] = -1e30f; mprev[mf][1] = -1e30f;
        lsum[mf][0] = 0.f;     lsum[mf][1] = 0.f;
    }

    attn_fill(KsB, VsB, MsB, Kg, Vg, mg, 0, tid);
    CP_COMMIT();

    const int nkt = SEQ / 64;
    for (int kt = 0; kt < nkt; kt++) {
        CP_WAIT0();
        __syncthreads();

        const int cur = kt & 1;
        if (kt + 1 < nkt) {
            const int nxt = (kt + 1) & 1;
            attn_fill(KsB + (uint32_t)(nxt * 64 * KST * 2),
                      VsB + (uint32_t)(nxt * 64 * VST * 2),
                      MsB + (uint32_t)(nxt * 256),
                      Kg, Vg, mg, kt + 1, tid);
        }
        CP_COMMIT();

        const uint32_t ksB = KsB + (uint32_t)(cur * 64 * KST * 2);
        const uint32_t vsB = VsB + (uint32_t)(cur * 64 * VST * 2);
        const int*     ms_ = Ms + cur * 64;

        float s[2][8][4];
#pragma unroll
        for (int mf = 0; mf < 2; mf++)
#pragma unroll
            for (int nf = 0; nf < 8; nf++)
#pragma unroll
                for (int r = 0; r < 4; r++) s[mf][nf][r] = 0.f;

#pragma unroll
        for (int kb = 0; kb < 4; kb++) {
#pragma unroll
            for (int nfp = 0; nfp < 4; nfp++) {
                uint32_t addr = ksB + (uint32_t)(
                    (((nfp * 2 + (mquad >> 1)) * 8 + mrow) * KST
                     + kb * 16 + (mquad & 1) * 8) * 2);
                uint32_t b0, b1, b2, b3;
                LDSM4(b0, b1, b2, b3, addr);
                mma_f16(s[0][2 * nfp],     qa[0][kb], b0, b1);
                mma_f16(s[0][2 * nfp + 1], qa[0][kb], b2, b3);
                mma_f16(s[1][2 * nfp],     qa[1][kb], b0, b1);
                mma_f16(s[1][2 * nfp + 1], qa[1][kb], b2, b3);
            }
        }

#pragma unroll
        for (int nf = 0; nf < 8; nf++) {
            const int nc = nf * 8 + 2 * c0;
            const bool k0m = ms_[nc] != 0, k1m = ms_[nc + 1] != 0;
#pragma unroll
            for (int mf = 0; mf < 2; mf++) {
                s[mf][nf][0] = k0m ? s[mf][nf][0] : -1e9f;
                s[mf][nf][1] = k1m ? s[mf][nf][1] : -1e9f;
                s[mf][nf][2] = k0m ? s[mf][nf][2] : -1e9f;
                s[mf][nf][3] = k1m ? s[mf][nf][3] : -1e9f;
            }
        }

#pragma unroll
        for (int mf = 0; mf < 2; mf++) {
            float rmax0 = -1e30f, rmax1 = -1e30f;
#pragma unroll
            for (int nf = 0; nf < 8; nf++) {
                rmax0 = fmaxf(rmax0, fmaxf(s[mf][nf][0], s[mf][nf][1]));
                rmax1 = fmaxf(rmax1, fmaxf(s[mf][nf][2], s[mf][nf][3]));
            }
            rmax0 = fmaxf(rmax0, __shfl_xor_sync(0xffffffffu, rmax0, 1));
            rmax0 = fmaxf(rmax0, __shfl_xor_sync(0xffffffffu, rmax0, 2));
            rmax1 = fmaxf(rmax1, __shfl_xor_sync(0xffffffffu, rmax1, 1));
            rmax1 = fmaxf(rmax1, __shfl_xor_sync(0xffffffffu, rmax1, 2));

            const float mn0 = fmaxf(mprev[mf][0], rmax0);
            const float mn1 = fmaxf(mprev[mf][1], rmax1);
            const float fac0 = ex2(mprev[mf][0] - mn0);
            const float fac1 = ex2(mprev[mf][1] - mn1);

            float rs0 = 0.f, rs1 = 0.f;
#pragma unroll
            for (int nf = 0; nf < 8; nf++) {
                s[mf][nf][0] = ex2(s[mf][nf][0] - mn0);
                s[mf][nf][1] = ex2(s[mf][nf][1] - mn0);
                s[mf][nf][2] = ex2(s[mf][nf][2] - mn1);
                s[mf][nf][3] = ex2(s[mf][nf][3] - mn1);
                rs0 += s[mf][nf][0] + s[mf][nf][1];
                rs1 += s[mf][nf][2] + s[mf][nf][3];
            }
            rs0 += __shfl_xor_sync(0xffffffffu, rs0, 1);
            rs0 += __shfl_xor_sync(0xffffffffu, rs0, 2);
            rs1 += __shfl_xor_sync(0xffffffffu, rs1, 1);
            rs1 += __shfl_xor_sync(0xffffffffu, rs1, 2);

            lsum[mf][0] = lsum[mf][0] * fac0 + rs0;
            lsum[mf][1] = lsum[mf][1] * fac1 + rs1;
            mprev[mf][0] = mn0; mprev[mf][1] = mn1;
#pragma unroll
            for (int df = 0; df < 8; df++) {
                o[mf][df][0] *= fac0; o[mf][df][1] *= fac0;
                o[mf][df][2] *= fac1; o[mf][df][3] *= fac1;
            }
        }

        uint32_t pa[2][4][4];
#pragma unroll
        for (int mf = 0; mf < 2; mf++)
#pragma unroll
            for (int kb = 0; kb < 4; kb++) {
                pa[mf][kb][0] = pkh2(s[mf][2 * kb][0],     s[mf][2 * kb][1]);
                pa[mf][kb][1] = pkh2(s[mf][2 * kb][2],     s[mf][2 * kb][3]);
                pa[mf][kb][2] = pkh2(s[mf][2 * kb + 1][0], s[mf][2 * kb + 1][1]);
                pa[mf][kb][3] = pkh2(s[mf][2 * kb + 1][2], s[mf][2 * kb + 1][3]);
            }

#pragma unroll
        for (int kb = 0; kb < 4; kb++) {
#pragma unroll
            for (int dfp = 0; dfp < 4; dfp++) {
                uint32_t addr = vsB + (uint32_t)(
                    ((kb * 16 + (mquad & 1) * 8 + mrow) * VST
                     + (dfp * 2 + (mquad >> 1)) * 8) * 2);
                uint32_t b0, b1, b2, b3;
                LDSM4T(b0, b1, b2, b3, addr);
                mma_f16(o[0][2 * dfp],     pa[0][kb], b0, b1);
                mma_f16(o[0][2 * dfp + 1], pa[0][kb], b2, b3);
                mma_f16(o[1][2 * dfp],     pa[1][kb], b0, b1);
                mma_f16(o[1][2 * dfp + 1], pa[1][kb], b2, b3);
            }
        }
    }

#pragma unroll
    for (int mf = 0; mf < 2; mf++) {
        const float inv0 = (lsum[mf][0] > 0.f) ? (1.f / lsum[mf][0]) : 0.f;
        const float inv1 = (lsum[mf][1] > 0.f) ? (1.f / lsum[mf][1]) : 0.f;
        const int q0 = qt * 128 + wid * 32 + mf * 16 + r0;
#pragma unroll
        for (int df = 0; df < 8; df++) {
            const int d = df * 8 + 2 * c0;
            __half2 h0 = __floats2half2_rn(o[mf][df][0] * inv0, o[mf][df][1] * inv0);
            __half2 h1 = __floats2half2_rn(o[mf][df][2] * inv1, o[mf][df][3] * inv1);
            *(__half2*)(ctx + ((size_t)(b * SEQ + q0) * H_HEADS + h) * 64 + d) = h0;
            *(__half2*)(ctx + ((size_t)(b * SEQ + q0 + 8) * H_HEADS + h) * 64 + d) = h1;
        }
    }
}

// ============================================================================
// launch
// ============================================================================
extern "C" void kernel_launch(void* const* d_in, const int* in_sizes, int n_in,
                              void* d_out, int out_size)
{
    const float* query = (const float*)d_in[0];
    const float* key_  = (const float*)d_in[1];
    const float* value = (const float*)d_in[2];
    const int*   mask  = (const int*)  d_in[3];
    const float* Wq = (const float*)d_in[4];
    const float* bq = (const float*)d_in[5];
    const float* Wk = (const float*)d_in[6];
    const float* bk = (const float*)d_in[7];
    const float* Wv = (const float*)d_in[8];
    const float* bv = (const float*)d_in[9];
    const float* Wo = (const float*)d_in[10];
    const float* bo = (const float*)d_in[11];
    float* out = (float*)d_out;

    __half *gq, *gk, *gv, *gctx, *gain, *gwin;
    cudaGetSymbolAddress((void**)&gq,   g_q);
    cudaGetSymbolAddress((void**)&gk,   g_k);
    cudaGetSymbolAddress((void**)&gv,   g_v);
    cudaGetSymbolAddress((void**)&gctx, g_ctx);
    cudaGetSymbolAddress((void**)&gain, g_ain);
    cudaGetSymbolAddress((void**)&gwin, g_win);

    __half* aq = gain;
    __half* ak = gain + (size_t)MTOT * DMODEL;
    __half* av = gain + 2 * (size_t)MTOT * DMODEL;
    __half* wq = gwin;
    __half* wk = gwin + (size_t)DMODEL * DMODEL;
    __half* wv = gwin + 2 * (size_t)DMODEL * DMODEL;
    __half* wo = gwin + 3 * (size_t)DMODEL * DMODEL;

    cudaFuncSetAttribute(gemm_mma,
                         cudaFuncAttributeMaxDynamicSharedMemorySize, GEMM_SMEM);
    cudaFuncSetAttribute(gemm_qkv,
                         cudaFuncAttributeMaxDynamicSharedMemorySize, GEMM_SMEM);
    cudaFuncSetAttribute(attn_mma,
                         cudaFuncAttributeMaxDynamicSharedMemorySize, ATT_SMEM);

    // ---- fused fp16 conversion prepass (4 float4 / thread) ----
    round_all<<<PRE_BLKS, 256>>>(query, key_, value, Wq, Wk, Wv, Wo);

    // ---- fused Q/K/V projections ----
    dim3 qkvgrid(DMODEL / 128, MTOT / 128, 3);    // (8, 64, 3)
    gemm_qkv<<<qkvgrid, dim3(128), GEMM_SMEM>>>(aq, ak, av, wq, wk, wv,
                                                bq, bk, bv, gq, gk, gv);

    // ---- attention (fp16 m16n8k16) ----
    dim3 agrid(SEQ / 128, H_HEADS, BATCH);        // (16, 16, 4)
    attn_mma<<<agrid, dim3(128), ATT_SMEM>>>(gq, gk, gv, mask, gctx);

    // ---- output projection ----
    dim3 ggrid(DMODEL / 128, MTOT / 128);         // (8, 64)
    gemm_mma<<<ggrid, dim3(128), GEMM_SMEM>>>(gctx, wo, bo, out);
}